// round 1
// baseline (speedup 1.0000x reference)
#include <cuda_runtime.h>
#include <math.h>

// ---------------- problem constants ----------------
#define N1   8192
#define N2   4096
#define TT   15
#define BS   4
#define E1C  131072
#define E2C  65536
#define KCH  12
#define G1C  64
#define G2C  32
#define NC   6

// ---------------- float scratch layout ----------------
#define T1_STRIDE (N1*64)                         // 524288 (channels padded 60->64)
#define OFF_T1    0                               // 3 buffers
#define OFF_Y1    (OFF_T1 + 3*T1_STRIDE)          // N1*256
#define T2_STRIDE (N2*256)
#define OFF_T2    (OFF_Y1 + N1*256)               // 3 buffers (buf0 = GEMM output h2)
#define OFF_Y2    (OFF_T2 + 3*T2_STRIDE)          // N2*128
#define OFF_NORM1 (OFF_Y2 + N2*128)
#define OFF_NORM2 (OFF_NORM1 + E1C)
#define OFF_DEG1  (OFF_NORM2 + E2C)
#define OFF_DEG2  (OFF_DEG1 + N1)
#define OFF_LOG   (OFF_DEG2 + N2)
#define SCRATCH_F (OFF_LOG + 64)

__device__ float g_f[SCRATCH_F];

// ---------------- int scratch layout ----------------
#define IO_FLAG  0
#define IO_RP1   1
#define IO_CU1   (IO_RP1 + N1 + 1)
#define IO_EI1   (IO_CU1 + N1)
#define IO_SRC1  (IO_EI1 + E1C)
#define IO_DST1  (IO_SRC1 + E1C)
#define IO_RP2   (IO_DST1 + E1C)
#define IO_CU2   (IO_RP2 + N2 + 1)
#define IO_EI2   (IO_CU2 + N2)
#define IO_SRC2  (IO_EI2 + E2C)
#define IO_DST2  (IO_SRC2 + E2C)
#define SCRATCH_I (IO_DST2 + E2C)

__device__ int g_i[SCRATCH_I];

// ================= preprocessing =================

__global__ void k_zero_counts() {
    int i = blockIdx.x * blockDim.x + threadIdx.x;
    if (i == 0) g_i[IO_FLAG] = 0;
    if (i < N1) g_i[IO_CU1 + i] = 0;
    if (i < N2) g_i[IO_CU2 + i] = 0;
}

// Detect whether edge_index is stored as int64 or int32.
// Read the FIRST E slots as int64 (safe under both layouts). If data is really
// int32, adjacent pairs combine into huge values -> flag=1 (int32).
__global__ void k_detect(const long long* p, int E, int n) {
    int e = blockIdx.x * blockDim.x + threadIdx.x;
    if (e < E) {
        long long v = p[e];
        if (v < 0 || v >= (long long)n) atomicOr(&g_i[IO_FLAG], 1);
    }
}

__global__ void k_decode(const void* eiv, int E, int srcOff, int dstOff) {
    int e = blockIdx.x * blockDim.x + threadIdx.x;
    if (e >= E) return;
    int is32 = g_i[IO_FLAG];
    int s, d;
    if (is32) {
        const int* p = (const int*)eiv;
        s = p[e]; d = p[E + e];
    } else {
        const long long* p = (const long long*)eiv;
        s = (int)p[e]; d = (int)p[E + e];
    }
    g_i[srcOff + e] = s;
    g_i[dstOff + e] = d;
}

__global__ void k_count(int E, int dstOff, int cursOff) {
    int e = blockIdx.x * blockDim.x + threadIdx.x;
    if (e < E) atomicAdd(&g_i[cursOff + g_i[dstOff + e]], 1);
}

// single-block exclusive scan over n counts (in curs array); writes rowptr and
// resets curs[i] = rowptr[i] (cursor for fill phase).
__global__ void k_scan(int n, int cntOff, int rpOff) {
    __shared__ int part[1024];
    int t = threadIdx.x;
    int chunk = (n + 1023) >> 10;
    int base = t * chunk;
    int s = 0;
    for (int i = 0; i < chunk; i++) { int idx = base + i; if (idx < n) s += g_i[cntOff + idx]; }
    part[t] = s;
    __syncthreads();
    for (int off = 1; off < 1024; off <<= 1) {
        int v = (t >= off) ? part[t - off] : 0;
        __syncthreads();
        part[t] += v;
        __syncthreads();
    }
    int run = (t > 0) ? part[t - 1] : 0;
    for (int i = 0; i < chunk; i++) {
        int idx = base + i;
        if (idx < n) {
            int v = g_i[cntOff + idx];
            g_i[rpOff + idx] = run;
            g_i[cntOff + idx] = run;
            run += v;
        }
    }
    if (t == 1023) g_i[rpOff + n] = part[1023];
}

__global__ void k_fill(int E, int dstOff, int cursOff, int eidOff) {
    int e = blockIdx.x * blockDim.x + threadIdx.x;
    if (e < E) {
        int d = g_i[dstOff + e];
        int p = atomicAdd(&g_i[cursOff + d], 1);
        g_i[eidOff + p] = e;
    }
}

// deterministic within-row order: sort each CSR row by edge id
__global__ void k_sortrows(int n, int rpOff, int eidOff) {
    int node = blockIdx.x * blockDim.x + threadIdx.x;
    if (node >= n) return;
    int beg = g_i[rpOff + node], end = g_i[rpOff + node + 1];
    for (int i = beg + 1; i < end; i++) {
        int key = g_i[eidOff + i];
        int j = i - 1;
        while (j >= beg && g_i[eidOff + j] > key) {
            g_i[eidOff + j + 1] = g_i[eidOff + j];
            j--;
        }
        g_i[eidOff + j + 1] = key;
    }
}

__global__ void k_deg(int n, int rpOff, int eidOff, const float* w, int degOff) {
    int node = blockIdx.x * blockDim.x + threadIdx.x;
    if (node >= n) return;
    int beg = g_i[rpOff + node], end = g_i[rpOff + node + 1];
    float s = 0.f;
    for (int i = beg; i < end; i++) s += w[g_i[eidOff + i]];
    g_f[degOff + node] = s;
}

__global__ void k_norm(int E, int srcOff, int dstOff, const float* w, int degOff, int normOff) {
    int e = blockIdx.x * blockDim.x + threadIdx.x;
    if (e >= E) return;
    float ds = g_f[degOff + g_i[srcOff + e]];
    float dd = g_f[degOff + g_i[dstOff + e]];
    float rs = (ds > 0.f) ? rsqrtf(ds) : 0.f;
    float rd = (dd > 0.f) ? rsqrtf(dd) : 0.f;
    g_f[normOff + e] = -w[e] * rs * rd;
}

// x (B,N1,T) -> h0 (N1, 64) with j = d*4+b, padded d>=15 -> 0
__global__ void k_xpose(const float* x) {
    int n = blockIdx.x;
    int j = threadIdx.x;   // 64
    int d = j >> 2, b = j & 3;
    float v = (d < TT) ? x[(size_t)b * (N1 * TT) + n * TT + d] : 0.f;
    g_f[OFF_T1 + n * 64 + j] = v;
}

// ================= Chebyshev propagation (gather CSR) =================

// C=64 channels: warp per node; half-warps process alternating edges, combine with shfl.
__global__ void k_prop64(int inOff, int outOff, int prevOff, int dbl,
                         int srcOff, int rpOff, int eidOff, int normOff) {
    int warp = (blockIdx.x * blockDim.x + threadIdx.x) >> 5;
    int lane = threadIdx.x & 31;
    int half = lane >> 4, c4 = lane & 15;
    int beg = g_i[rpOff + warp], end = g_i[rpOff + warp + 1];
    const float4* in = (const float4*)(g_f + inOff);
    float4 acc = make_float4(0.f, 0.f, 0.f, 0.f);
    for (int i = beg + half; i < end; i += 2) {
        int e = g_i[eidOff + i];
        float nm = g_f[normOff + e];
        int s = g_i[srcOff + e];
        float4 v = in[s * 16 + c4];
        acc.x = fmaf(nm, v.x, acc.x);
        acc.y = fmaf(nm, v.y, acc.y);
        acc.z = fmaf(nm, v.z, acc.z);
        acc.w = fmaf(nm, v.w, acc.w);
    }
    acc.x += __shfl_down_sync(0xffffffffu, acc.x, 16);
    acc.y += __shfl_down_sync(0xffffffffu, acc.y, 16);
    acc.z += __shfl_down_sync(0xffffffffu, acc.z, 16);
    acc.w += __shfl_down_sync(0xffffffffu, acc.w, 16);
    if (half == 0) {
        float4 r = acc;
        if (dbl) {
            float4 p = ((const float4*)(g_f + prevOff))[warp * 16 + c4];
            r.x = 2.f * r.x - p.x;
            r.y = 2.f * r.y - p.y;
            r.z = 2.f * r.z - p.z;
            r.w = 2.f * r.w - p.w;
        }
        ((float4*)(g_f + outOff))[warp * 16 + c4] = r;
    }
}

// C=256 channels: warp per node, 2 float4 per lane.
__global__ void k_prop256(int inOff, int outOff, int prevOff, int dbl,
                          int srcOff, int rpOff, int eidOff, int normOff) {
    int node = (blockIdx.x * blockDim.x + threadIdx.x) >> 5;
    int lane = threadIdx.x & 31;
    int beg = g_i[rpOff + node], end = g_i[rpOff + node + 1];
    const float4* in = (const float4*)(g_f + inOff);
    float4 a0 = make_float4(0.f, 0.f, 0.f, 0.f);
    float4 a1 = a0;
    for (int i = beg; i < end; i++) {
        int e = g_i[eidOff + i];
        float nm = g_f[normOff + e];
        int s = g_i[srcOff + e];
        const float4* row = in + s * 64;
        float4 v0 = row[lane], v1 = row[lane + 32];
        a0.x = fmaf(nm, v0.x, a0.x); a0.y = fmaf(nm, v0.y, a0.y);
        a0.z = fmaf(nm, v0.z, a0.z); a0.w = fmaf(nm, v0.w, a0.w);
        a1.x = fmaf(nm, v1.x, a1.x); a1.y = fmaf(nm, v1.y, a1.y);
        a1.z = fmaf(nm, v1.z, a1.z); a1.w = fmaf(nm, v1.w, a1.w);
    }
    if (dbl) {
        const float4* pv = (const float4*)(g_f + prevOff) + node * 64;
        float4 p0 = pv[lane], p1 = pv[lane + 32];
        a0.x = 2.f * a0.x - p0.x; a0.y = 2.f * a0.y - p0.y;
        a0.z = 2.f * a0.z - p0.z; a0.w = 2.f * a0.w - p0.w;
        a1.x = 2.f * a1.x - p1.x; a1.y = 2.f * a1.y - p1.y;
        a1.z = 2.f * a1.z - p1.z; a1.w = 2.f * a1.w - p1.w;
    }
    float4* o = (float4*)(g_f + outOff) + node * 64;
    o[lane] = a0;
    o[lane + 32] = a1;
}

// ================= per-k einsums =================

// y1[n, g*4+b] (+)= sum_d T[n,d,b] * W1[k,d,g]; 4 nodes per block, 256 threads
__global__ void k_ein1(int tOff, const float* W1, const float* bias1, int k, int first) {
    __shared__ float sW[TT * G1C];
    __shared__ float sT[256];
    int tid = threadIdx.x;
    int n0 = blockIdx.x * 4;
    const float* Wk = W1 + k * TT * G1C;
    for (int i = tid; i < TT * G1C; i += 256) sW[i] = Wk[i];
    sT[tid] = g_f[tOff + n0 * 64 + tid];
    __syncthreads();
    int g = tid >> 2, b = tid & 3;
    for (int ns = 0; ns < 4; ns++) {
        float s = 0.f;
#pragma unroll
        for (int d = 0; d < TT; d++) s = fmaf(sT[ns * 64 + d * 4 + b], sW[d * G1C + g], s);
        int idx = OFF_Y1 + (n0 + ns) * 256 + tid;
        if (first) g_f[idx] = s + bias1[g];
        else       g_f[idx] += s;
    }
}

// y2[n, g*4+b] (+)= sum_d T[n,d,b] * W2[k,d,g]; 2 nodes per block, 256 threads
__global__ void k_ein2(int tOff, const float* W2, const float* bias2, int k, int first) {
    __shared__ float sW[G1C * G2C];
    __shared__ float sT[512];
    int tid = threadIdx.x;
    int n0 = blockIdx.x * 2;
    const float* Wk = W2 + k * G1C * G2C;
    for (int i = tid; i < G1C * G2C; i += 256) sW[i] = Wk[i];
    sT[tid] = g_f[tOff + n0 * 256 + tid];
    sT[tid + 256] = g_f[tOff + n0 * 256 + tid + 256];
    __syncthreads();
    int local = tid & 127, ns = tid >> 7;
    int g = local >> 2, b = local & 3;
    float s = 0.f;
#pragma unroll
    for (int d = 0; d < G1C; d++) s = fmaf(sT[ns * 256 + d * 4 + b], sW[d * G2C + g], s);
    int idx = OFF_Y2 + (n0 + ns) * 128 + local;
    if (first) g_f[idx] = s + bias2[g];
    else       g_f[idx] += s;
}

__global__ void k_relu() {
    int i = blockIdx.x * blockDim.x + threadIdx.x;
    if (i < N1 * 256) g_f[OFF_Y1 + i] = fmaxf(g_f[OFF_Y1 + i], 0.f);
}

// ================= b_map GEMM: h2(4096x256) = A(4096x8192) * y1(8192x256) =================
// fp32 SIMT tiled: BM=BN=64, BK=16, 256 threads, 4x4 per thread
__global__ void k_gemm(const float* __restrict__ A) {
    __shared__ float sA[16][64];
    __shared__ float sB[16][64];
    int tid = threadIdx.x;
    int bm = blockIdx.y * 64, bn = blockIdx.x * 64;
    int rA = tid >> 2, cA4 = (tid & 3) * 4;
    int rB = tid >> 4, cB4 = (tid & 15) * 4;
    int tmr = (tid >> 4) << 2, tnr = (tid & 15) << 2;
    const float* Bm = g_f + OFF_Y1;
    float acc[4][4] = {};
    for (int k0 = 0; k0 < N1; k0 += 16) {
        float4 av = *(const float4*)&A[(size_t)(bm + rA) * N1 + k0 + cA4];
        sA[cA4 + 0][rA] = av.x;
        sA[cA4 + 1][rA] = av.y;
        sA[cA4 + 2][rA] = av.z;
        sA[cA4 + 3][rA] = av.w;
        *(float4*)&sB[rB][cB4] = *(const float4*)&Bm[(size_t)(k0 + rB) * 256 + bn + cB4];
        __syncthreads();
#pragma unroll
        for (int kk = 0; kk < 16; kk++) {
            float4 a = *(const float4*)&sA[kk][tmr];
            float4 b = *(const float4*)&sB[kk][tnr];
            acc[0][0] = fmaf(a.x, b.x, acc[0][0]); acc[0][1] = fmaf(a.x, b.y, acc[0][1]);
            acc[0][2] = fmaf(a.x, b.z, acc[0][2]); acc[0][3] = fmaf(a.x, b.w, acc[0][3]);
            acc[1][0] = fmaf(a.y, b.x, acc[1][0]); acc[1][1] = fmaf(a.y, b.y, acc[1][1]);
            acc[1][2] = fmaf(a.y, b.z, acc[1][2]); acc[1][3] = fmaf(a.y, b.w, acc[1][3]);
            acc[2][0] = fmaf(a.z, b.x, acc[2][0]); acc[2][1] = fmaf(a.z, b.y, acc[2][1]);
            acc[2][2] = fmaf(a.z, b.z, acc[2][2]); acc[2][3] = fmaf(a.z, b.w, acc[2][3]);
            acc[3][0] = fmaf(a.w, b.x, acc[3][0]); acc[3][1] = fmaf(a.w, b.y, acc[3][1]);
            acc[3][2] = fmaf(a.w, b.z, acc[3][2]); acc[3][3] = fmaf(a.w, b.w, acc[3][3]);
        }
        __syncthreads();
    }
    float* Cp = g_f + OFF_T2;  // conv2 buf0 = h2
#pragma unroll
    for (int i = 0; i < 4; i++) {
        float4 v = make_float4(acc[i][0], acc[i][1], acc[i][2], acc[i][3]);
        *(float4*)&Cp[(size_t)(bm + tmr + i) * 256 + bn + tnr] = v;
    }
}

// ================= classifier =================

__global__ void k_fc(const float* __restrict__ fcw, const float* __restrict__ fcb) {
    int q = blockIdx.x / 6, c = blockIdx.x % 6;
    __shared__ float red[256];
    const float* y = g_f + OFF_Y2 + (size_t)q * 131072;
    const float* w = fcw + (size_t)c * 131072;
    float s = 0.f;
    for (int j = threadIdx.x; j < 131072; j += 256) s = fmaf(y[j], w[j], s);
    red[threadIdx.x] = s;
    __syncthreads();
    for (int o = 128; o > 0; o >>= 1) {
        if (threadIdx.x < o) red[threadIdx.x] += red[threadIdx.x + o];
        __syncthreads();
    }
    if (threadIdx.x == 0) g_f[OFF_LOG + q * 6 + c] = red[0] + fcb[c];
}

__global__ void k_lsm(float* out) {
    int t = threadIdx.x;
    if (t < 4) {
        float v[6];
        float m = -1e30f;
        for (int c = 0; c < 6; c++) { v[c] = g_f[OFF_LOG + t * 6 + c]; m = fmaxf(m, v[c]); }
        float se = 0.f;
        for (int c = 0; c < 6; c++) se += expf(v[c] - m);
        float l = logf(se);
        for (int c = 0; c < 6; c++) out[t * 6 + c] = v[c] - m - l;
    }
}

// ================= host =================

extern "C" void kernel_launch(void* const* d_in, const int* in_sizes, int n_in,
                              void* d_out, int out_size) {
    const float*     x    = (const float*)d_in[0];
    const void*      ei1  = d_in[1];
    const float*     w1e  = (const float*)d_in[2];
    const void*      ei2  = d_in[3];
    const float*     w2e  = (const float*)d_in[4];
    const float*     bmap = (const float*)d_in[5];
    const float*     W1   = (const float*)d_in[6];
    const float*     bias1= (const float*)d_in[7];
    const float*     W2   = (const float*)d_in[8];
    const float*     bias2= (const float*)d_in[9];
    const float*     fcw  = (const float*)d_in[10];
    const float*     fcb  = (const float*)d_in[11];
    float*           out  = (float*)d_out;
    (void)in_sizes; (void)n_in; (void)out_size;

    // --- preprocessing ---
    k_zero_counts<<<(N1 + 255) / 256, 256>>>();
    k_detect<<<(E1C + 255) / 256, 256>>>((const long long*)ei1, E1C, N1);
    k_decode<<<(E1C + 255) / 256, 256>>>(ei1, E1C, IO_SRC1, IO_DST1);
    k_decode<<<(E2C + 255) / 256, 256>>>(ei2, E2C, IO_SRC2, IO_DST2);
    k_count<<<(E1C + 255) / 256, 256>>>(E1C, IO_DST1, IO_CU1);
    k_count<<<(E2C + 255) / 256, 256>>>(E2C, IO_DST2, IO_CU2);
    k_scan<<<1, 1024>>>(N1, IO_CU1, IO_RP1);
    k_scan<<<1, 1024>>>(N2, IO_CU2, IO_RP2);
    k_fill<<<(E1C + 255) / 256, 256>>>(E1C, IO_DST1, IO_CU1, IO_EI1);
    k_fill<<<(E2C + 255) / 256, 256>>>(E2C, IO_DST2, IO_CU2, IO_EI2);
    k_sortrows<<<(N1 + 127) / 128, 128>>>(N1, IO_RP1, IO_EI1);
    k_sortrows<<<(N2 + 127) / 128, 128>>>(N2, IO_RP2, IO_EI2);
    k_deg<<<(N1 + 127) / 128, 128>>>(N1, IO_RP1, IO_EI1, w1e, OFF_DEG1);
    k_deg<<<(N2 + 127) / 128, 128>>>(N2, IO_RP2, IO_EI2, w2e, OFF_DEG2);
    k_norm<<<(E1C + 255) / 256, 256>>>(E1C, IO_SRC1, IO_DST1, w1e, OFF_DEG1, OFF_NORM1);
    k_norm<<<(E2C + 255) / 256, 256>>>(E2C, IO_SRC2, IO_DST2, w2e, OFF_DEG2, OFF_NORM2);
    k_xpose<<<N1, 64>>>(x);

    // --- conv1: Chebyshev K=12 on graph1 ---
    int b1buf[3] = {OFF_T1, OFF_T1 + T1_STRIDE, OFF_T1 + 2 * T1_STRIDE};
    k_ein1<<<N1 / 4, 256>>>(b1buf[0], W1, bias1, 0, 1);
    k_prop64<<<N1 / 8, 256>>>(b1buf[0], b1buf[1], 0, 0, IO_SRC1, IO_RP1, IO_EI1, OFF_NORM1);
    k_ein1<<<N1 / 4, 256>>>(b1buf[1], W1, bias1, 1, 0);
    for (int k = 2; k < KCH; k++) {
        int in = b1buf[(k - 1) % 3], o = b1buf[k % 3], pv = b1buf[(k - 2) % 3];
        k_prop64<<<N1 / 8, 256>>>(in, o, pv, 1, IO_SRC1, IO_RP1, IO_EI1, OFF_NORM1);
        k_ein1<<<N1 / 4, 256>>>(o, W1, bias1, k, 0);
    }
    k_relu<<<(N1 * 256 + 255) / 256, 256>>>();

    // --- b_map GEMM -> conv2 buf0 ---
    dim3 gg(4, 64);
    k_gemm<<<gg, 256>>>(bmap);

    // --- conv2: Chebyshev K=12 on graph2 ---
    int b2buf[3] = {OFF_T2, OFF_T2 + T2_STRIDE, OFF_T2 + 2 * T2_STRIDE};
    k_ein2<<<N2 / 2, 256>>>(b2buf[0], W2, bias2, 0, 1);
    k_prop256<<<N2 / 8, 256>>>(b2buf[0], b2buf[1], 0, 0, IO_SRC2, IO_RP2, IO_EI2, OFF_NORM2);
    k_ein2<<<N2 / 2, 256>>>(b2buf[1], W2, bias2, 1, 0);
    for (int k = 2; k < KCH; k++) {
        int in = b2buf[(k - 1) % 3], o = b2buf[k % 3], pv = b2buf[(k - 2) % 3];
        k_prop256<<<N2 / 8, 256>>>(in, o, pv, 1, IO_SRC2, IO_RP2, IO_EI2, OFF_NORM2);
        k_ein2<<<N2 / 2, 256>>>(o, W2, bias2, k, 0);
    }

    // --- fc + log_softmax ---
    k_fc<<<24, 256>>>(fcw, fcb);
    k_lsm<<<1, 32>>>(out);
}

// round 5
// speedup vs baseline: 1.5500x; 1.5500x over previous
#include <cuda_runtime.h>
#include <cuda_bf16.h>
#include <cstdint>
#include <stdint.h>
#include <math.h>

// ---------------- problem constants ----------------
#define N1   8192
#define N2   4096
#define TT   15
#define BS   4
#define E1C  131072
#define E2C  65536
#define KCH  12
#define G1C  64
#define G2C  32
#define NC   6

// ---------------- float scratch layout ----------------
#define T1_STRIDE (N1*64)
#define OFF_T1    0
#define OFF_Y1    (OFF_T1 + 3*T1_STRIDE)
#define T2_STRIDE (N2*256)
#define OFF_T2    (OFF_Y1 + N1*256)
#define OFF_Y2    (OFF_T2 + 3*T2_STRIDE)
#define OFF_NORM1 (OFF_Y2 + N2*128)
#define OFF_NORM2 (OFF_NORM1 + E1C)
#define OFF_DEG1  (OFF_NORM2 + E2C)
#define OFF_DEG2  (OFF_DEG1 + N1)
#define OFF_LOG   (OFF_DEG2 + N2)
#define OFF_PART  (OFF_LOG + 64)
#define SCRATCH_F (OFF_PART + 4*N2*256)

__device__ float g_f[SCRATCH_F];

// bf16 split buffers for the tensor-core GEMM (plain row-major)
__device__ __nv_bfloat16 g_Ahi[(size_t)N2 * N1];   // [4096][8192]
__device__ __nv_bfloat16 g_Alo[(size_t)N2 * N1];
__device__ __nv_bfloat16 g_Bthi[(size_t)256 * N1]; // B^T: [256][8192]
__device__ __nv_bfloat16 g_Btlo[(size_t)256 * N1];

// ---------------- int scratch layout ----------------
#define IO_FLAG  0
#define IO_RP1   1
#define IO_CU1   (IO_RP1 + N1 + 1)
#define IO_EI1   (IO_CU1 + N1)
#define IO_SRC1  (IO_EI1 + E1C)
#define IO_DST1  (IO_SRC1 + E1C)
#define IO_RP2   (IO_DST1 + E1C)
#define IO_CU2   (IO_RP2 + N2 + 1)
#define IO_EI2   (IO_CU2 + N2)
#define IO_SRC2  (IO_EI2 + E2C)
#define IO_DST2  (IO_SRC2 + E2C)
#define SCRATCH_I (IO_DST2 + E2C)

__device__ int g_i[SCRATCH_I];

// ================= helpers =================

__device__ __forceinline__ uint32_t smem_u32(const void* p) {
    uint32_t a;
    asm("{ .reg .u64 t; cvta.to.shared.u64 t, %1; cvt.u32.u64 %0, t; }" : "=r"(a) : "l"(p));
    return a;
}

#define CP16(dst, src) \
    asm volatile("cp.async.cg.shared.global [%0], [%1], 16;" :: "r"(dst), "l"(src))
#define CP_COMMIT() asm volatile("cp.async.commit_group;" ::: "memory")
#define CP_WAIT1()  asm volatile("cp.async.wait_group 1;" ::: "memory")

#define LDS32(v, a) asm volatile("ld.shared.b32 %0, [%1];" : "=r"(v) : "r"(a))

#define MMA_BF16(c, a, b) \
    asm volatile("mma.sync.aligned.m16n8k16.row.col.f32.bf16.bf16.f32 " \
        "{%0,%1,%2,%3}, {%4,%5,%6,%7}, {%8,%9}, {%0,%1,%2,%3};" \
        : "+f"((c)[0]), "+f"((c)[1]), "+f"((c)[2]), "+f"((c)[3]) \
        : "r"((a)[0]), "r"((a)[1]), "r"((a)[2]), "r"((a)[3]), \
          "r"((b)[0]), "r"((b)[1]))

// ================= preprocessing =================

__global__ void k_zero_counts() {
    int i = blockIdx.x * blockDim.x + threadIdx.x;
    if (i == 0) g_i[IO_FLAG] = 0;
    if (i < N1) g_i[IO_CU1 + i] = 0;
    if (i < N2) g_i[IO_CU2 + i] = 0;
}

__global__ void k_detect(const long long* p, int E, int n) {
    int e = blockIdx.x * blockDim.x + threadIdx.x;
    if (e < E) {
        long long v = p[e];
        if (v < 0 || v >= (long long)n) atomicOr(&g_i[IO_FLAG], 1);
    }
}

__global__ void k_decode(const void* eiv, int E, int srcOff, int dstOff) {
    int e = blockIdx.x * blockDim.x + threadIdx.x;
    if (e >= E) return;
    int is32 = g_i[IO_FLAG];
    int s, d;
    if (is32) {
        const int* p = (const int*)eiv;
        s = p[e]; d = p[E + e];
    } else {
        const long long* p = (const long long*)eiv;
        s = (int)p[e]; d = (int)p[E + e];
    }
    g_i[srcOff + e] = s;
    g_i[dstOff + e] = d;
}

__global__ void k_count(int E, int dstOff, int cursOff) {
    int e = blockIdx.x * blockDim.x + threadIdx.x;
    if (e < E) atomicAdd(&g_i[cursOff + g_i[dstOff + e]], 1);
}

__global__ void k_scan(int n, int cntOff, int rpOff) {
    __shared__ int part[1024];
    int t = threadIdx.x;
    int chunk = (n + 1023) >> 10;
    int base = t * chunk;
    int s = 0;
    for (int i = 0; i < chunk; i++) { int idx = base + i; if (idx < n) s += g_i[cntOff + idx]; }
    part[t] = s;
    __syncthreads();
    for (int off = 1; off < 1024; off <<= 1) {
        int v = (t >= off) ? part[t - off] : 0;
        __syncthreads();
        part[t] += v;
        __syncthreads();
    }
    int run = (t > 0) ? part[t - 1] : 0;
    for (int i = 0; i < chunk; i++) {
        int idx = base + i;
        if (idx < n) {
            int v = g_i[cntOff + idx];
            g_i[rpOff + idx] = run;
            g_i[cntOff + idx] = run;
            run += v;
        }
    }
    if (t == 1023) g_i[rpOff + n] = part[1023];
}

__global__ void k_fill(int E, int dstOff, int cursOff, int eidOff) {
    int e = blockIdx.x * blockDim.x + threadIdx.x;
    if (e < E) {
        int d = g_i[dstOff + e];
        int p = atomicAdd(&g_i[cursOff + d], 1);
        g_i[eidOff + p] = e;
    }
}

__global__ void k_sortrows(int n, int rpOff, int eidOff) {
    int node = blockIdx.x * blockDim.x + threadIdx.x;
    if (node >= n) return;
    int beg = g_i[rpOff + node], end = g_i[rpOff + node + 1];
    for (int i = beg + 1; i < end; i++) {
        int key = g_i[eidOff + i];
        int j = i - 1;
        while (j >= beg && g_i[eidOff + j] > key) {
            g_i[eidOff + j + 1] = g_i[eidOff + j];
            j--;
        }
        g_i[eidOff + j + 1] = key;
    }
}

__global__ void k_deg(int n, int rpOff, int eidOff, const float* w, int degOff) {
    int node = blockIdx.x * blockDim.x + threadIdx.x;
    if (node >= n) return;
    int beg = g_i[rpOff + node], end = g_i[rpOff + node + 1];
    float s = 0.f;
    for (int i = beg; i < end; i++) s += w[g_i[eidOff + i]];
    g_f[degOff + node] = s;
}

__global__ void k_norm(int E, int srcOff, int dstOff, const float* w, int degOff, int normOff) {
    int e = blockIdx.x * blockDim.x + threadIdx.x;
    if (e >= E) return;
    float ds = g_f[degOff + g_i[srcOff + e]];
    float dd = g_f[degOff + g_i[dstOff + e]];
    float rs = (ds > 0.f) ? rsqrtf(ds) : 0.f;
    float rd = (dd > 0.f) ? rsqrtf(dd) : 0.f;
    g_f[normOff + e] = -w[e] * rs * rd;
}

__global__ void k_xpose(const float* x) {
    int n = blockIdx.x;
    int j = threadIdx.x;
    int d = j >> 2, b = j & 3;
    float v = (d < TT) ? x[(size_t)b * (N1 * TT) + n * TT + d] : 0.f;
    g_f[OFF_T1 + n * 64 + j] = v;
}

// ================= Chebyshev propagation (gather CSR) =================

__global__ void k_prop64(int inOff, int outOff, int prevOff, int dbl,
                         int srcOff, int rpOff, int eidOff, int normOff) {
    int warp = (blockIdx.x * blockDim.x + threadIdx.x) >> 5;
    int lane = threadIdx.x & 31;
    int half = lane >> 4, c4 = lane & 15;
    int beg = g_i[rpOff + warp], end = g_i[rpOff + warp + 1];
    const float4* in = (const float4*)(g_f + inOff);
    float4 acc = make_float4(0.f, 0.f, 0.f, 0.f);
    for (int i = beg + half; i < end; i += 2) {
        int e = g_i[eidOff + i];
        float nm = g_f[normOff + e];
        int s = g_i[srcOff + e];
        float4 v = in[s * 16 + c4];
        acc.x = fmaf(nm, v.x, acc.x);
        acc.y = fmaf(nm, v.y, acc.y);
        acc.z = fmaf(nm, v.z, acc.z);
        acc.w = fmaf(nm, v.w, acc.w);
    }
    acc.x += __shfl_down_sync(0xffffffffu, acc.x, 16);
    acc.y += __shfl_down_sync(0xffffffffu, acc.y, 16);
    acc.z += __shfl_down_sync(0xffffffffu, acc.z, 16);
    acc.w += __shfl_down_sync(0xffffffffu, acc.w, 16);
    if (half == 0) {
        float4 r = acc;
        if (dbl) {
            float4 p = ((const float4*)(g_f + prevOff))[warp * 16 + c4];
            r.x = 2.f * r.x - p.x;
            r.y = 2.f * r.y - p.y;
            r.z = 2.f * r.z - p.z;
            r.w = 2.f * r.w - p.w;
        }
        ((float4*)(g_f + outOff))[warp * 16 + c4] = r;
    }
}

__global__ void k_prop256(int inOff, int outOff, int prevOff, int dbl,
                          int srcOff, int rpOff, int eidOff, int normOff) {
    int node = (blockIdx.x * blockDim.x + threadIdx.x) >> 5;
    int lane = threadIdx.x & 31;
    int beg = g_i[rpOff + node], end = g_i[rpOff + node + 1];
    const float4* in = (const float4*)(g_f + inOff);
    float4 a0 = make_float4(0.f, 0.f, 0.f, 0.f);
    float4 a1 = a0;
    for (int i = beg; i < end; i++) {
        int e = g_i[eidOff + i];
        float nm = g_f[normOff + e];
        int s = g_i[srcOff + e];
        const float4* row = in + s * 64;
        float4 v0 = row[lane], v1 = row[lane + 32];
        a0.x = fmaf(nm, v0.x, a0.x); a0.y = fmaf(nm, v0.y, a0.y);
        a0.z = fmaf(nm, v0.z, a0.z); a0.w = fmaf(nm, v0.w, a0.w);
        a1.x = fmaf(nm, v1.x, a1.x); a1.y = fmaf(nm, v1.y, a1.y);
        a1.z = fmaf(nm, v1.z, a1.z); a1.w = fmaf(nm, v1.w, a1.w);
    }
    if (dbl) {
        const float4* pv = (const float4*)(g_f + prevOff) + node * 64;
        float4 p0 = pv[lane], p1 = pv[lane + 32];
        a0.x = 2.f * a0.x - p0.x; a0.y = 2.f * a0.y - p0.y;
        a0.z = 2.f * a0.z - p0.z; a0.w = 2.f * a0.w - p0.w;
        a1.x = 2.f * a1.x - p1.x; a1.y = 2.f * a1.y - p1.y;
        a1.z = 2.f * a1.z - p1.z; a1.w = 2.f * a1.w - p1.w;
    }
    float4* o = (float4*)(g_f + outOff) + node * 64;
    o[lane] = a0;
    o[lane + 32] = a1;
}

// ================= per-k einsums =================

__global__ void k_ein1(int tOff, const float* W1, const float* bias1, int k, int first) {
    __shared__ float sW[TT * G1C];
    __shared__ float sT[256];
    int tid = threadIdx.x;
    int n0 = blockIdx.x * 4;
    const float* Wk = W1 + k * TT * G1C;
    for (int i = tid; i < TT * G1C; i += 256) sW[i] = Wk[i];
    sT[tid] = g_f[tOff + n0 * 64 + tid];
    __syncthreads();
    int g = tid >> 2, b = tid & 3;
    for (int ns = 0; ns < 4; ns++) {
        float s = 0.f;
#pragma unroll
        for (int d = 0; d < TT; d++) s = fmaf(sT[ns * 64 + d * 4 + b], sW[d * G1C + g], s);
        int idx = OFF_Y1 + (n0 + ns) * 256 + tid;
        if (first) g_f[idx] = s + bias1[g];
        else       g_f[idx] += s;
    }
}

__global__ void k_ein2(int tOff, const float* W2, const float* bias2, int k, int first) {
    __shared__ float sW[G1C * G2C];
    __shared__ float sT[512];
    int tid = threadIdx.x;
    int n0 = blockIdx.x * 2;
    const float* Wk = W2 + k * G1C * G2C;
    for (int i = tid; i < G1C * G2C; i += 256) sW[i] = Wk[i];
    sT[tid] = g_f[tOff + n0 * 256 + tid];
    sT[tid + 256] = g_f[tOff + n0 * 256 + tid + 256];
    __syncthreads();
    int local = tid & 127, ns = tid >> 7;
    int g = local >> 2, b = local & 3;
    float s = 0.f;
#pragma unroll
    for (int d = 0; d < G1C; d++) s = fmaf(sT[ns * 256 + d * 4 + b], sW[d * G2C + g], s);
    int idx = OFF_Y2 + (n0 + ns) * 128 + local;
    if (first) g_f[idx] = s + bias2[g];
    else       g_f[idx] += s;
}

// ================= split-bf16 conversion =================

// A (b_map): elementwise split into hi/lo, plain row-major
__global__ void k_convA(const float* __restrict__ A) {
    size_t i = ((size_t)blockIdx.x * 256 + threadIdx.x) * 8;
    float4 v0 = *(const float4*)&A[i];
    float4 v1 = *(const float4*)&A[i + 4];
    float vv[8] = {v0.x, v0.y, v0.z, v0.w, v1.x, v1.y, v1.z, v1.w};
    unsigned short h[8], l[8];
#pragma unroll
    for (int q = 0; q < 8; q++) {
        h[q] = __bfloat16_as_ushort(__float2bfloat16(vv[q]));
        float r = vv[q] - __bfloat162float(__ushort_as_bfloat16(h[q]));
        l[q] = __bfloat16_as_ushort(__float2bfloat16(r));
    }
    uint4 uh = make_uint4((uint32_t)h[0] | ((uint32_t)h[1] << 16),
                          (uint32_t)h[2] | ((uint32_t)h[3] << 16),
                          (uint32_t)h[4] | ((uint32_t)h[5] << 16),
                          (uint32_t)h[6] | ((uint32_t)h[7] << 16));
    uint4 ul = make_uint4((uint32_t)l[0] | ((uint32_t)l[1] << 16),
                          (uint32_t)l[2] | ((uint32_t)l[3] << 16),
                          (uint32_t)l[4] | ((uint32_t)l[5] << 16),
                          (uint32_t)l[6] | ((uint32_t)l[7] << 16));
    *(uint4*)((char*)g_Ahi + i * 2) = uh;
    *(uint4*)((char*)g_Alo + i * 2) = ul;
}

// B^T = relu(y1)^T: y1 [8192][256] fp32 -> Bt hi/lo [256][8192] bf16 (relu fused)
__global__ void k_convBT() {
    __shared__ float s[64][65];
    int kt = blockIdx.x >> 2, nt = blockIdx.x & 3;
    int k0 = kt * 64, n0 = nt * 64;
    int t = threadIdx.x;
    {
        int r = t >> 4, c4 = t & 15;
#pragma unroll
        for (int i = 0; i < 4; i++) {
            int row = r + i * 16;
            float4 v = *(const float4*)&g_f[OFF_Y1 + (size_t)(k0 + row) * 256 + n0 + c4 * 4];
            s[row][c4 * 4 + 0] = fmaxf(v.x, 0.f);
            s[row][c4 * 4 + 1] = fmaxf(v.y, 0.f);
            s[row][c4 * 4 + 2] = fmaxf(v.z, 0.f);
            s[row][c4 * 4 + 3] = fmaxf(v.w, 0.f);
        }
    }
    __syncthreads();
    int n = t >> 2, kc = t & 3;
    unsigned short h[16], l[16];
#pragma unroll
    for (int e = 0; e < 16; e++) {
        float v = s[kc * 16 + e][n];
        h[e] = __bfloat16_as_ushort(__float2bfloat16(v));
        float r = v - __bfloat162float(__ushort_as_bfloat16(h[e]));
        l[e] = __bfloat16_as_ushort(__float2bfloat16(r));
    }
    size_t ob = (size_t)(n0 + n) * N1 + k0 + kc * 16;
    uint4* dh = (uint4*)(g_Bthi + ob);
    uint4* dl = (uint4*)(g_Btlo + ob);
#pragma unroll
    for (int half = 0; half < 2; half++) {
        int e0 = half * 8;
        dh[half] = make_uint4((uint32_t)h[e0] | ((uint32_t)h[e0+1] << 16),
                              (uint32_t)h[e0+2] | ((uint32_t)h[e0+3] << 16),
                              (uint32_t)h[e0+4] | ((uint32_t)h[e0+5] << 16),
                              (uint32_t)h[e0+6] | ((uint32_t)h[e0+7] << 16));
        dl[half] = make_uint4((uint32_t)l[e0] | ((uint32_t)l[e0+1] << 16),
                              (uint32_t)l[e0+2] | ((uint32_t)l[e0+3] << 16),
                              (uint32_t)l[e0+4] | ((uint32_t)l[e0+5] << 16),
                              (uint32_t)l[e0+6] | ((uint32_t)l[e0+7] << 16));
    }
}

// ================= mma.sync split-bf16 GEMM =================
// C(4096x256) = A(4096x8192) * B(8192x256), 3-product split-bf16, fp32 acc.
// Grid (nt=2, mt=32, ks=2). CTA 128x128 tile, K slice 4096, 16 warps (warp 32x32).
// smem stage: Ahi[128][32] (+pad rows 80B) | Alo | Bthi[128 n][32 k] | Btlo; 2 stages.

#define SA_H 0
#define SA_L 10240
#define SB_H 20480
#define SB_L 30720
#define GSTAGE 40960
#define GSM_TOTAL (2 * GSTAGE)
#define NKCHUNK 128   // 4096 / 32

__global__ void __launch_bounds__(512, 1) k_gemm_mma() {
    extern __shared__ char smem[];
    uint32_t sb = smem_u32(smem);
    int tid = threadIdx.x, lane = tid & 31, wid = tid >> 5;
    int nt = blockIdx.x, mt = blockIdx.y, ks = blockIdx.z;
    int bm = mt * 128, bn = nt * 128;
    int kbase = ks * 4096;

    const __nv_bfloat16* Ah = g_Ahi;
    const __nv_bfloat16* Al = g_Alo;
    const __nv_bfloat16* Bh = g_Bthi;
    const __nv_bfloat16* Bl = g_Btlo;

    int lrow = tid >> 2, lch = tid & 3;  // 128 rows x 4 chunks of 16B

#define LOADSTAGE(kc, st) do { \
        int koff_ = kbase + (kc) * 32 + lch * 8; \
        uint32_t db_ = sb + (st) * GSTAGE + lrow * 80 + lch * 16; \
        CP16(db_ + SA_H, Ah + (size_t)(bm + lrow) * N1 + koff_); \
        CP16(db_ + SA_L, Al + (size_t)(bm + lrow) * N1 + koff_); \
        CP16(db_ + SB_H, Bh + (size_t)(bn + lrow) * N1 + koff_); \
        CP16(db_ + SB_L, Bl + (size_t)(bn + lrow) * N1 + koff_); \
    } while (0)

    LOADSTAGE(0, 0); CP_COMMIT();
    LOADSTAGE(1, 1); CP_COMMIT();

    int mw = wid & 3, nw = wid >> 2;  // warp tile: rows mw*32, cols nw*32
    float acc[2][4][4];
#pragma unroll
    for (int f = 0; f < 2; f++)
#pragma unroll
        for (int g = 0; g < 4; g++)
#pragma unroll
            for (int q = 0; q < 4; q++) acc[f][g][q] = 0.f;

    int qrow = lane >> 2, qk = (lane & 3) * 2;

    for (int kc = 0; kc < NKCHUNK; kc++) {
        int st = kc & 1;
        CP_WAIT1();
        __syncthreads();
        uint32_t base = sb + st * GSTAGE;
#pragma unroll
        for (int kk = 0; kk < 32; kk += 16) {
            uint32_t ah[2][4], al[2][4];
#pragma unroll
            for (int f = 0; f < 2; f++) {
                uint32_t a0 = base + (mw * 32 + f * 16 + qrow) * 80 + (qk + kk) * 2;
                LDS32(ah[f][0], a0 + SA_H);
                LDS32(ah[f][1], a0 + SA_H + 8 * 80);
                LDS32(ah[f][2], a0 + SA_H + 16);
                LDS32(ah[f][3], a0 + SA_H + 8 * 80 + 16);
                LDS32(al[f][0], a0 + SA_L);
                LDS32(al[f][1], a0 + SA_L + 8 * 80);
                LDS32(al[f][2], a0 + SA_L + 16);
                LDS32(al[f][3], a0 + SA_L + 8 * 80 + 16);
            }
#pragma unroll
            for (int g = 0; g < 4; g++) {
                uint32_t bh[2], bl[2];
                uint32_t b0 = base + (nw * 32 + g * 8 + qrow) * 80 + (qk + kk) * 2;
                LDS32(bh[0], b0 + SB_H);
                LDS32(bh[1], b0 + SB_H + 16);
                LDS32(bl[0], b0 + SB_L);
                LDS32(bl[1], b0 + SB_L + 16);
#pragma unroll
                for (int f = 0; f < 2; f++) {
                    MMA_BF16(acc[f][g], ah[f], bh);
                    MMA_BF16(acc[f][g], ah[f], bl);
                    MMA_BF16(acc[f][g], al[f], bh);
                }
            }
        }
        __syncthreads();
        if (kc + 2 < NKCHUNK) LOADSTAGE(kc + 2, st);
        CP_COMMIT();
    }
#undef LOADSTAGE

    // epilogue: write fp32 partials
    float* part = g_f + OFF_PART + (size_t)ks * (N2 * 256);
#pragma unroll
    for (int f = 0; f < 2; f++) {
        int row = bm + mw * 32 + f * 16 + qrow;
#pragma unroll
        for (int g = 0; g < 4; g++) {
            int col = bn + nw * 32 + g * 8 + (lane & 3) * 2;
            *(float2*)&part[(size_t)row * 256 + col] = make_float2(acc[f][g][0], acc[f][g][1]);
            *(float2*)&part[(size_t)(row + 8) * 256 + col] = make_float2(acc[f][g][2], acc[f][g][3]);
        }
    }
}

// reduce 2 K-split partials -> h2 (conv2 buf0)
__global__ void k_red() {
    int i = blockIdx.x * blockDim.x + threadIdx.x;
    const float4* p0 = (const float4*)(g_f + OFF_PART);
    const float4* p1 = (const float4*)(g_f + OFF_PART + N2 * 256);
    float4 a = p0[i], b = p1[i];
    ((float4*)(g_f + OFF_T2))[i] = make_float4(a.x + b.x, a.y + b.y, a.z + b.z, a.w + b.w);
}

// ================= classifier =================

__global__ void k_fc(const float* __restrict__ fcw, const float* __restrict__ fcb) {
    int q = blockIdx.x / 6, c = blockIdx.x % 6;
    __shared__ float red[256];
    const float* y = g_f + OFF_Y2 + (size_t)q * 131072;
    const float* w = fcw + (size_t)c * 131072;
    float s = 0.f;
    for (int j = threadIdx.x; j < 131072; j += 256) s = fmaf(y[j], w[j], s);
    red[threadIdx.x] = s;
    __syncthreads();
    for (int o = 128; o > 0; o >>= 1) {
        if (threadIdx.x < o) red[threadIdx.x] += red[threadIdx.x + o];
        __syncthreads();
    }
    if (threadIdx.x == 0) g_f[OFF_LOG + q * 6 + c] = red[0] + fcb[c];
}

__global__ void k_lsm(float* out) {
    int t = threadIdx.x;
    if (t < 4) {
        float v[6];
        float m = -1e30f;
        for (int c = 0; c < 6; c++) { v[c] = g_f[OFF_LOG + t * 6 + c]; m = fmaxf(m, v[c]); }
        float se = 0.f;
        for (int c = 0; c < 6; c++) se += expf(v[c] - m);
        float l = logf(se);
        for (int c = 0; c < 6; c++) out[t * 6 + c] = v[c] - m - l;
    }
}

// ================= host =================

extern "C" void kernel_launch(void* const* d_in, const int* in_sizes, int n_in,
                              void* d_out, int out_size) {
    const float*     x    = (const float*)d_in[0];
    const void*      ei1  = d_in[1];
    const float*     w1e  = (const float*)d_in[2];
    const void*      ei2  = d_in[3];
    const float*     w2e  = (const float*)d_in[4];
    const float*     bmap = (const float*)d_in[5];
    const float*     W1   = (const float*)d_in[6];
    const float*     bias1= (const float*)d_in[7];
    const float*     W2   = (const float*)d_in[8];
    const float*     bias2= (const float*)d_in[9];
    const float*     fcw  = (const float*)d_in[10];
    const float*     fcb  = (const float*)d_in[11];
    float*           out  = (float*)d_out;
    (void)in_sizes; (void)n_in; (void)out_size;

    cudaFuncSetAttribute(k_gemm_mma, cudaFuncAttributeMaxDynamicSharedMemorySize, GSM_TOTAL);

    // --- preprocessing ---
    k_zero_counts<<<(N1 + 255) / 256, 256>>>();
    k_detect<<<(E1C + 255) / 256, 256>>>((const long long*)ei1, E1C, N1);
    k_decode<<<(E1C + 255) / 256, 256>>>(ei1, E1C, IO_SRC1, IO_DST1);
    k_decode<<<(E2C + 255) / 256, 256>>>(ei2, E2C, IO_SRC2, IO_DST2);
    k_count<<<(E1C + 255) / 256, 256>>>(E1C, IO_DST1, IO_CU1);
    k_count<<<(E2C + 255) / 256, 256>>>(E2C, IO_DST2, IO_CU2);
    k_scan<<<1, 1024>>>(N1, IO_CU1, IO_RP1);
    k_scan<<<1, 1024>>>(N2, IO_CU2, IO_RP2);
    k_fill<<<(E1C + 255) / 256, 256>>>(E1C, IO_DST1, IO_CU1, IO_EI1);
    k_fill<<<(E2C + 255) / 256, 256>>>(E2C, IO_DST2, IO_CU2, IO_EI2);
    k_sortrows<<<(N1 + 127) / 128, 128>>>(N1, IO_RP1, IO_EI1);
    k_sortrows<<<(N2 + 127) / 128, 128>>>(N2, IO_RP2, IO_EI2);
    k_deg<<<(N1 + 127) / 128, 128>>>(N1, IO_RP1, IO_EI1, w1e, OFF_DEG1);
    k_deg<<<(N2 + 127) / 128, 128>>>(N2, IO_RP2, IO_EI2, w2e, OFF_DEG2);
    k_norm<<<(E1C + 255) / 256, 256>>>(E1C, IO_SRC1, IO_DST1, w1e, OFF_DEG1, OFF_NORM1);
    k_norm<<<(E2C + 255) / 256, 256>>>(E2C, IO_SRC2, IO_DST2, w2e, OFF_DEG2, OFF_NORM2);
    k_xpose<<<N1, 64>>>(x);
    k_convA<<<16384, 256>>>(bmap);   // independent of conv1

    // --- conv1: Chebyshev K=12 on graph1 ---
    int b1buf[3] = {OFF_T1, OFF_T1 + T1_STRIDE, OFF_T1 + 2 * T1_STRIDE};
    k_ein1<<<N1 / 4, 256>>>(b1buf[0], W1, bias1, 0, 1);
    k_prop64<<<N1 / 8, 256>>>(b1buf[0], b1buf[1], 0, 0, IO_SRC1, IO_RP1, IO_EI1, OFF_NORM1);
    k_ein1<<<N1 / 4, 256>>>(b1buf[1], W1, bias1, 1, 0);
    for (int k = 2; k < KCH; k++) {
        int in = b1buf[(k - 1) % 3], o = b1buf[k % 3], pv = b1buf[(k - 2) % 3];
        k_prop64<<<N1 / 8, 256>>>(in, o, pv, 1, IO_SRC1, IO_RP1, IO_EI1, OFF_NORM1);
        k_ein1<<<N1 / 4, 256>>>(o, W1, bias1, k, 0);
    }

    // --- split-bf16 mma GEMM -> conv2 buf0 (relu fused into convBT) ---
    k_convBT<<<512, 256>>>();
    dim3 gg(2, 32, 2);
    k_gemm_mma<<<gg, 512, GSM_TOTAL>>>();
    k_red<<<1024, 256>>>();

    // --- conv2: Chebyshev K=12 on graph2 ---
    int b2buf[3] = {OFF_T2, OFF_T2 + T2_STRIDE, OFF_T2 + 2 * T2_STRIDE};
    k_ein2<<<N2 / 2, 256>>>(b2buf[0], W2, bias2, 0, 1);
    k_prop256<<<N2 / 8, 256>>>(b2buf[0], b2buf[1], 0, 0, IO_SRC2, IO_RP2, IO_EI2, OFF_NORM2);
    k_ein2<<<N2 / 2, 256>>>(b2buf[1], W2, bias2, 1, 0);
    for (int k = 2; k < KCH; k++) {
        int in = b2buf[(k - 1) % 3], o = b2buf[k % 3], pv = b2buf[(k - 2) % 3];
        k_prop256<<<N2 / 8, 256>>>(in, o, pv, 1, IO_SRC2, IO_RP2, IO_EI2, OFF_NORM2);
        k_ein2<<<N2 / 2, 256>>>(o, W2, bias2, k, 0);
    }

    // --- fc + log_softmax ---
    k_fc<<<24, 256>>>(fcw, fcb);
    k_lsm<<<1, 32>>>(out);
}

// round 6
// speedup vs baseline: 1.8388x; 1.1863x over previous
#include <cuda_runtime.h>
#include <cuda_bf16.h>
#include <cstdint>
#include <stdint.h>
#include <math.h>

// ---------------- problem constants ----------------
#define N1   8192
#define N2   4096
#define TT   15
#define BS   4
#define E1C  131072
#define E2C  65536
#define KCH  12
#define G1C  64
#define G2C  32
#define NC   6

// ---------------- float scratch layout ----------------
#define T1_STRIDE (N1*64)
#define OFF_T1    0
#define OFF_Y1    (OFF_T1 + 3*T1_STRIDE)
#define T2_STRIDE (N2*256)
#define OFF_T2    (OFF_Y1 + N1*256)
#define OFF_Y2    (OFF_T2 + 3*T2_STRIDE)
#define OFF_NORM1 (OFF_Y2 + N2*128)
#define OFF_NORM2 (OFF_NORM1 + E1C)
#define OFF_DEG1  (OFF_NORM2 + E2C)
#define OFF_DEG2  (OFF_DEG1 + N1)
#define OFF_LOG   (OFF_DEG2 + N2)
#define OFF_PART  (OFF_LOG + 64)
#define SCRATCH_F (OFF_PART + 4*N2*256)

__device__ float g_f[SCRATCH_F];

// bf16 split buffers for the tensor-core GEMM (plain row-major)
__device__ __nv_bfloat16 g_Ahi[(size_t)N2 * N1];   // [4096][8192]
__device__ __nv_bfloat16 g_Alo[(size_t)N2 * N1];
__device__ __nv_bfloat16 g_Bthi[(size_t)256 * N1]; // B^T: [256][8192]
__device__ __nv_bfloat16 g_Btlo[(size_t)256 * N1];

// ---------------- int scratch layout ----------------
#define IO_FLAG  0
#define IO_RP1   1
#define IO_CU1   (IO_RP1 + N1 + 1)
#define IO_EI1   (IO_CU1 + N1)
#define IO_SRC1  (IO_EI1 + E1C)
#define IO_DST1  (IO_SRC1 + E1C)
#define IO_RP2   (IO_DST1 + E1C)
#define IO_CU2   (IO_RP2 + N2 + 1)
#define IO_EI2   (IO_CU2 + N2)
#define IO_SRC2  (IO_EI2 + E2C)
#define IO_DST2  (IO_SRC2 + E2C)
#define SCRATCH_I (IO_DST2 + E2C)

__device__ int g_i[SCRATCH_I];

// ================= helpers =================

__device__ __forceinline__ uint32_t smem_u32(const void* p) {
    uint32_t a;
    asm("{ .reg .u64 t; cvta.to.shared.u64 t, %1; cvt.u32.u64 %0, t; }" : "=r"(a) : "l"(p));
    return a;
}

#define CP16(dst, src) \
    asm volatile("cp.async.cg.shared.global [%0], [%1], 16;" :: "r"(dst), "l"(src))
#define CP_COMMIT() asm volatile("cp.async.commit_group;" ::: "memory")
#define CP_WAIT1()  asm volatile("cp.async.wait_group 1;" ::: "memory")

#define LDS32(v, a) asm volatile("ld.shared.b32 %0, [%1];" : "=r"(v) : "r"(a))

#define MMA_BF16(c, a, b) \
    asm volatile("mma.sync.aligned.m16n8k16.row.col.f32.bf16.bf16.f32 " \
        "{%0,%1,%2,%3}, {%4,%5,%6,%7}, {%8,%9}, {%0,%1,%2,%3};" \
        : "+f"((c)[0]), "+f"((c)[1]), "+f"((c)[2]), "+f"((c)[3]) \
        : "r"((a)[0]), "r"((a)[1]), "r"((a)[2]), "r"((a)[3]), \
          "r"((b)[0]), "r"((b)[1]))

// ================= preprocessing (merged) =================

__global__ void k_zero() {
    int i = blockIdx.x * blockDim.x + threadIdx.x;
    if (i == 0) g_i[IO_FLAG] = 0;
    if (i < N1) g_i[IO_CU1 + i] = 0;
    if (i < N2) g_i[IO_CU2 + i] = 0;
}

__global__ void k_detect(const long long* p) {
    int e = blockIdx.x * blockDim.x + threadIdx.x;
    if (e < E1C) {
        long long v = p[e];
        if (v < 0 || v >= (long long)N1) atomicOr(&g_i[IO_FLAG], 1);
    }
}

__global__ void k_decode2(const void* ei1, const void* ei2) {
    int e = blockIdx.x * blockDim.x + threadIdx.x;
    int is32 = g_i[IO_FLAG];
    const void* eiv; int E, srcOff, dstOff, le;
    if (e < E1C) { eiv = ei1; E = E1C; srcOff = IO_SRC1; dstOff = IO_DST1; le = e; }
    else if (e < E1C + E2C) { eiv = ei2; E = E2C; srcOff = IO_SRC2; dstOff = IO_DST2; le = e - E1C; }
    else return;
    int s, d;
    if (is32) {
        const int* p = (const int*)eiv;
        s = p[le]; d = p[E + le];
    } else {
        const long long* p = (const long long*)eiv;
        s = (int)p[le]; d = (int)p[E + le];
    }
    g_i[srcOff + le] = s;
    g_i[dstOff + le] = d;
}

__global__ void k_count2() {
    int e = blockIdx.x * blockDim.x + threadIdx.x;
    if (e < E1C) atomicAdd(&g_i[IO_CU1 + g_i[IO_DST1 + e]], 1);
    else if (e < E1C + E2C) atomicAdd(&g_i[IO_CU2 + g_i[IO_DST2 + e - E1C]], 1);
}

__global__ void k_scan2() {
    __shared__ int part[1024];
    int n, cntOff, rpOff;
    if (blockIdx.x == 0) { n = N1; cntOff = IO_CU1; rpOff = IO_RP1; }
    else                 { n = N2; cntOff = IO_CU2; rpOff = IO_RP2; }
    int t = threadIdx.x;
    int chunk = (n + 1023) >> 10;
    int base = t * chunk;
    int s = 0;
    for (int i = 0; i < chunk; i++) { int idx = base + i; if (idx < n) s += g_i[cntOff + idx]; }
    part[t] = s;
    __syncthreads();
    for (int off = 1; off < 1024; off <<= 1) {
        int v = (t >= off) ? part[t - off] : 0;
        __syncthreads();
        part[t] += v;
        __syncthreads();
    }
    int run = (t > 0) ? part[t - 1] : 0;
    for (int i = 0; i < chunk; i++) {
        int idx = base + i;
        if (idx < n) {
            int v = g_i[cntOff + idx];
            g_i[rpOff + idx] = run;
            g_i[cntOff + idx] = run;
            run += v;
        }
    }
    if (t == 1023) g_i[rpOff + n] = part[1023];
}

__global__ void k_fill2() {
    int e = blockIdx.x * blockDim.x + threadIdx.x;
    if (e < E1C) {
        int d = g_i[IO_DST1 + e];
        int p = atomicAdd(&g_i[IO_CU1 + d], 1);
        g_i[IO_EI1 + p] = e;
    } else if (e < E1C + E2C) {
        int le = e - E1C;
        int d = g_i[IO_DST2 + le];
        int p = atomicAdd(&g_i[IO_CU2 + d], 1);
        g_i[IO_EI2 + p] = le;
    }
}

__global__ void k_sortdeg(const float* w1, const float* w2) {
    int idx = blockIdx.x * blockDim.x + threadIdx.x;
    int rpOff, eidOff, degOff, node;
    const float* w;
    if (idx < N1) { node = idx; rpOff = IO_RP1; eidOff = IO_EI1; degOff = OFF_DEG1; w = w1; }
    else if (idx < N1 + N2) { node = idx - N1; rpOff = IO_RP2; eidOff = IO_EI2; degOff = OFF_DEG2; w = w2; }
    else return;
    int beg = g_i[rpOff + node], end = g_i[rpOff + node + 1];
    for (int i = beg + 1; i < end; i++) {
        int key = g_i[eidOff + i];
        int j = i - 1;
        while (j >= beg && g_i[eidOff + j] > key) {
            g_i[eidOff + j + 1] = g_i[eidOff + j];
            j--;
        }
        g_i[eidOff + j + 1] = key;
    }
    float s = 0.f;
    for (int i = beg; i < end; i++) s += w[g_i[eidOff + i]];
    g_f[degOff + node] = s;
}

__global__ void k_norm2(const float* w1, const float* w2) {
    int e = blockIdx.x * blockDim.x + threadIdx.x;
    int srcOff, dstOff, degOff, normOff, le;
    const float* w;
    if (e < E1C) { le = e; srcOff = IO_SRC1; dstOff = IO_DST1; degOff = OFF_DEG1; normOff = OFF_NORM1; w = w1; }
    else if (e < E1C + E2C) { le = e - E1C; srcOff = IO_SRC2; dstOff = IO_DST2; degOff = OFF_DEG2; normOff = OFF_NORM2; w = w2; }
    else return;
    float ds = g_f[degOff + g_i[srcOff + le]];
    float dd = g_f[degOff + g_i[dstOff + le]];
    float rs = (ds > 0.f) ? rsqrtf(ds) : 0.f;
    float rd = (dd > 0.f) ? rsqrtf(dd) : 0.f;
    g_f[normOff + le] = -w[le] * rs * rd;
}

// ================= conv1: fused kernels =================

// xpose + ein(k=0): grid N1/8, 256 threads
__global__ void k_xpose_ein0(const float* __restrict__ x, const float* __restrict__ W1,
                             const float* __restrict__ bias1) {
    __shared__ float sW[TT * G1C];
    __shared__ float sT[8 * 64];
    int tid = threadIdx.x;
    int n0 = blockIdx.x * 8;
    for (int i = tid; i < TT * G1C; i += 256) sW[i] = W1[i];
#pragma unroll
    for (int it = 0; it < 2; it++) {
        int i = it * 256 + tid;
        int ns = i >> 6, j = i & 63;
        int d = j >> 2, b = j & 3;
        float v = (d < TT) ? x[(size_t)b * (N1 * TT) + (n0 + ns) * TT + d] : 0.f;
        sT[i] = v;
        g_f[OFF_T1 + (n0 + ns) * 64 + j] = v;
    }
    __syncthreads();
    int g = tid >> 2, b = tid & 3;
    float bv = bias1[g];
#pragma unroll
    for (int ns = 0; ns < 8; ns++) {
        float s = 0.f;
#pragma unroll
        for (int d = 0; d < TT; d++) s = fmaf(sT[ns * 64 + d * 4 + b], sW[d * G1C + g], s);
        g_f[OFF_Y1 + (n0 + ns) * 256 + tid] = s + bv;
    }
}

// fused prop + ein for conv1 step k: grid N1/8, 256 threads (8 warps = 8 nodes)
__global__ void k_step1(int inOff, int outOff, int prevOff, int dbl,
                        const float* __restrict__ W1, int k) {
    __shared__ float sW[TT * G1C];
    __shared__ float sT[8 * 64];
    int tid = threadIdx.x;
    for (int i = tid; i < TT * G1C; i += 256) sW[i] = W1[k * TT * G1C + i];
    int warp = tid >> 5, lane = tid & 31;
    int node = blockIdx.x * 8 + warp;
    int half = lane >> 4, c4 = lane & 15;
    int beg = g_i[IO_RP1 + node], end = g_i[IO_RP1 + node + 1];
    const float4* in = (const float4*)(g_f + inOff);
    float4 acc = make_float4(0.f, 0.f, 0.f, 0.f);
    for (int i = beg + half; i < end; i += 2) {
        int e = g_i[IO_EI1 + i];
        float nm = g_f[OFF_NORM1 + e];
        int s = g_i[IO_SRC1 + e];
        float4 v = in[s * 16 + c4];
        acc.x = fmaf(nm, v.x, acc.x);
        acc.y = fmaf(nm, v.y, acc.y);
        acc.z = fmaf(nm, v.z, acc.z);
        acc.w = fmaf(nm, v.w, acc.w);
    }
    acc.x += __shfl_down_sync(0xffffffffu, acc.x, 16);
    acc.y += __shfl_down_sync(0xffffffffu, acc.y, 16);
    acc.z += __shfl_down_sync(0xffffffffu, acc.z, 16);
    acc.w += __shfl_down_sync(0xffffffffu, acc.w, 16);
    if (half == 0) {
        float4 r = acc;
        if (dbl) {
            float4 p = ((const float4*)(g_f + prevOff))[node * 16 + c4];
            r.x = 2.f * r.x - p.x;
            r.y = 2.f * r.y - p.y;
            r.z = 2.f * r.z - p.z;
            r.w = 2.f * r.w - p.w;
        }
        ((float4*)(g_f + outOff))[node * 16 + c4] = r;
        *(float4*)&sT[warp * 64 + c4 * 4] = r;
    }
    __syncthreads();
    int g = tid >> 2, b = tid & 3;
    int n0 = blockIdx.x * 8;
#pragma unroll
    for (int ns = 0; ns < 8; ns++) {
        float s = 0.f;
#pragma unroll
        for (int d = 0; d < TT; d++) s = fmaf(sT[ns * 64 + d * 4 + b], sW[d * G1C + g], s);
        g_f[OFF_Y1 + (n0 + ns) * 256 + tid] += s;
    }
}

// ================= conv2: fused kernels =================

// reduce 4 GEMM partials -> T2 buf0 AND ein2(k=0): grid N2/8, 256 threads
__global__ void k_red_ein0(const float* __restrict__ W2, const float* __restrict__ bias2) {
    __shared__ float sW[G1C * G2C];
    __shared__ float sT[8 * 256];
    int tid = threadIdx.x;
    int n0 = blockIdx.x * 8;
    for (int i = tid; i < G1C * G2C; i += 256) sW[i] = W2[i];
#pragma unroll
    for (int ns = 0; ns < 8; ns++) {
        size_t gi = (size_t)(n0 + ns) * 256 + tid;
        float v = g_f[OFF_PART + gi] + g_f[OFF_PART + (N2 * 256) + gi]
                + g_f[OFF_PART + 2 * (N2 * 256) + gi] + g_f[OFF_PART + 3 * (N2 * 256) + gi];
        g_f[OFF_T2 + gi] = v;
        sT[ns * 256 + tid] = v;
    }
    __syncthreads();
    int local = tid & 127, sub = tid >> 7;
    int g = local >> 2, b = local & 3;
    float bv = bias2[g];
#pragma unroll
    for (int pass = 0; pass < 4; pass++) {
        int ns = pass * 2 + sub;
        float s = 0.f;
#pragma unroll
        for (int d = 0; d < G1C; d++) s = fmaf(sT[ns * 256 + d * 4 + b], sW[d * G2C + g], s);
        g_f[OFF_Y2 + (n0 + ns) * 128 + local] = s + bv;
    }
}

// fused prop + ein for conv2 step k: grid N2/8, 256 threads (8 warps = 8 nodes)
__global__ void k_step2(int inOff, int outOff, int prevOff, int dbl,
                        const float* __restrict__ W2, int k) {
    __shared__ float sW[G1C * G2C];
    __shared__ float sT[8 * 256];
    int tid = threadIdx.x;
    for (int i = tid; i < G1C * G2C; i += 256) sW[i] = W2[k * G1C * G2C + i];
    int warp = tid >> 5, lane = tid & 31;
    int node = blockIdx.x * 8 + warp;
    int beg = g_i[IO_RP2 + node], end = g_i[IO_RP2 + node + 1];
    const float4* in = (const float4*)(g_f + inOff);
    float4 a0 = make_float4(0.f, 0.f, 0.f, 0.f);
    float4 a1 = a0;
    for (int i = beg; i < end; i++) {
        int e = g_i[IO_EI2 + i];
        float nm = g_f[OFF_NORM2 + e];
        int s = g_i[IO_SRC2 + e];
        const float4* row = in + s * 64;
        float4 v0 = row[lane], v1 = row[lane + 32];
        a0.x = fmaf(nm, v0.x, a0.x); a0.y = fmaf(nm, v0.y, a0.y);
        a0.z = fmaf(nm, v0.z, a0.z); a0.w = fmaf(nm, v0.w, a0.w);
        a1.x = fmaf(nm, v1.x, a1.x); a1.y = fmaf(nm, v1.y, a1.y);
        a1.z = fmaf(nm, v1.z, a1.z); a1.w = fmaf(nm, v1.w, a1.w);
    }
    if (dbl) {
        const float4* pv = (const float4*)(g_f + prevOff) + node * 64;
        float4 p0 = pv[lane], p1 = pv[lane + 32];
        a0.x = 2.f * a0.x - p0.x; a0.y = 2.f * a0.y - p0.y;
        a0.z = 2.f * a0.z - p0.z; a0.w = 2.f * a0.w - p0.w;
        a1.x = 2.f * a1.x - p1.x; a1.y = 2.f * a1.y - p1.y;
        a1.z = 2.f * a1.z - p1.z; a1.w = 2.f * a1.w - p1.w;
    }
    float4* o = (float4*)(g_f + outOff) + node * 64;
    o[lane] = a0;
    o[lane + 32] = a1;
    *(float4*)&sT[warp * 256 + lane * 4] = a0;
    *(float4*)&sT[warp * 256 + 128 + lane * 4] = a1;
    __syncthreads();
    int local = tid & 127, sub = tid >> 7;
    int g = local >> 2, b = local & 3;
    int n0 = blockIdx.x * 8;
#pragma unroll
    for (int pass = 0; pass < 4; pass++) {
        int ns = pass * 2 + sub;
        float s = 0.f;
#pragma unroll
        for (int d = 0; d < G1C; d++) s = fmaf(sT[ns * 256 + d * 4 + b], sW[d * G2C + g], s);
        g_f[OFF_Y2 + (n0 + ns) * 128 + local] += s;
    }
}

// ================= split-bf16 conversion =================

__global__ void k_convA(const float* __restrict__ A) {
    size_t i = ((size_t)blockIdx.x * 256 + threadIdx.x) * 8;
    float4 v0 = *(const float4*)&A[i];
    float4 v1 = *(const float4*)&A[i + 4];
    float vv[8] = {v0.x, v0.y, v0.z, v0.w, v1.x, v1.y, v1.z, v1.w};
    unsigned short h[8], l[8];
#pragma unroll
    for (int q = 0; q < 8; q++) {
        h[q] = __bfloat16_as_ushort(__float2bfloat16(vv[q]));
        float r = vv[q] - __bfloat162float(__ushort_as_bfloat16(h[q]));
        l[q] = __bfloat16_as_ushort(__float2bfloat16(r));
    }
    uint4 uh = make_uint4((uint32_t)h[0] | ((uint32_t)h[1] << 16),
                          (uint32_t)h[2] | ((uint32_t)h[3] << 16),
                          (uint32_t)h[4] | ((uint32_t)h[5] << 16),
                          (uint32_t)h[6] | ((uint32_t)h[7] << 16));
    uint4 ul = make_uint4((uint32_t)l[0] | ((uint32_t)l[1] << 16),
                          (uint32_t)l[2] | ((uint32_t)l[3] << 16),
                          (uint32_t)l[4] | ((uint32_t)l[5] << 16),
                          (uint32_t)l[6] | ((uint32_t)l[7] << 16));
    *(uint4*)((char*)g_Ahi + i * 2) = uh;
    *(uint4*)((char*)g_Alo + i * 2) = ul;
}

// B^T = relu(y1)^T (relu fused)
__global__ void k_convBT() {
    __shared__ float s[64][65];
    int kt = blockIdx.x >> 2, nt = blockIdx.x & 3;
    int k0 = kt * 64, n0 = nt * 64;
    int t = threadIdx.x;
    {
        int r = t >> 4, c4 = t & 15;
#pragma unroll
        for (int i = 0; i < 4; i++) {
            int row = r + i * 16;
            float4 v = *(const float4*)&g_f[OFF_Y1 + (size_t)(k0 + row) * 256 + n0 + c4 * 4];
            s[row][c4 * 4 + 0] = fmaxf(v.x, 0.f);
            s[row][c4 * 4 + 1] = fmaxf(v.y, 0.f);
            s[row][c4 * 4 + 2] = fmaxf(v.z, 0.f);
            s[row][c4 * 4 + 3] = fmaxf(v.w, 0.f);
        }
    }
    __syncthreads();
    int n = t >> 2, kc = t & 3;
    unsigned short h[16], l[16];
#pragma unroll
    for (int e = 0; e < 16; e++) {
        float v = s[kc * 16 + e][n];
        h[e] = __bfloat16_as_ushort(__float2bfloat16(v));
        float r = v - __bfloat162float(__ushort_as_bfloat16(h[e]));
        l[e] = __bfloat16_as_ushort(__float2bfloat16(r));
    }
    size_t ob = (size_t)(n0 + n) * N1 + k0 + kc * 16;
    uint4* dh = (uint4*)(g_Bthi + ob);
    uint4* dl = (uint4*)(g_Btlo + ob);
#pragma unroll
    for (int half = 0; half < 2; half++) {
        int e0 = half * 8;
        dh[half] = make_uint4((uint32_t)h[e0] | ((uint32_t)h[e0+1] << 16),
                              (uint32_t)h[e0+2] | ((uint32_t)h[e0+3] << 16),
                              (uint32_t)h[e0+4] | ((uint32_t)h[e0+5] << 16),
                              (uint32_t)h[e0+6] | ((uint32_t)h[e0+7] << 16));
        dl[half] = make_uint4((uint32_t)l[e0] | ((uint32_t)l[e0+1] << 16),
                              (uint32_t)l[e0+2] | ((uint32_t)l[e0+3] << 16),
                              (uint32_t)l[e0+4] | ((uint32_t)l[e0+5] << 16),
                              (uint32_t)l[e0+6] | ((uint32_t)l[e0+7] << 16));
    }
}

// ================= mma.sync split-bf16 GEMM =================
// C(4096x256) = A(4096x8192) * B(8192x256), 3-product split-bf16, fp32 acc.
// Grid (mt=32, ks=4). CTA tile 128M x 256N, K slice 2048, 16 warps (warp 32x64).
// smem stage: Ahi[128][32]@80B rows | Alo | Bthi[256 n][32 k]@80B | Btlo; 2 stages.

#define SA_H 0
#define SA_L 10240
#define SB_H 20480
#define SB_L 40960
#define GSTAGE 61440
#define GSM_TOTAL (2 * GSTAGE)
#define NKCHUNK 64   // 2048 / 32

__global__ void __launch_bounds__(512, 1) k_gemm_mma() {
    extern __shared__ char smem[];
    uint32_t sb = smem_u32(smem);
    int tid = threadIdx.x, lane = tid & 31, wid = tid >> 5;
    int mt = blockIdx.x, ks = blockIdx.y;
    int bm = mt * 128;
    int kbase = ks * 2048;

    const __nv_bfloat16* Ah = g_Ahi;
    const __nv_bfloat16* Al = g_Alo;
    const __nv_bfloat16* Bh = g_Bthi;
    const __nv_bfloat16* Bl = g_Btlo;

    int arow = tid >> 2, ach = tid & 3;   // A: 128 rows x 4 chunks of 16B
    int brow = tid >> 1, bch = tid & 1;   // B: 256 rows x 2 chunk-pairs

#define LOADSTAGE(kc, st) do { \
        int ka_ = kbase + (kc) * 32 + ach * 8; \
        uint32_t da_ = sb + (st) * GSTAGE + arow * 80 + ach * 16; \
        CP16(da_ + SA_H, Ah + (size_t)(bm + arow) * N1 + ka_); \
        CP16(da_ + SA_L, Al + (size_t)(bm + arow) * N1 + ka_); \
        int kb_ = kbase + (kc) * 32 + bch * 16; \
        uint32_t db_ = sb + (st) * GSTAGE + brow * 80 + bch * 32; \
        CP16(db_ + SB_H,      Bh + (size_t)brow * N1 + kb_); \
        CP16(db_ + SB_H + 16, Bh + (size_t)brow * N1 + kb_ + 8); \
        CP16(db_ + SB_L,      Bl + (size_t)brow * N1 + kb_); \
        CP16(db_ + SB_L + 16, Bl + (size_t)brow * N1 + kb_ + 8); \
    } while (0)

    LOADSTAGE(0, 0); CP_COMMIT();
    LOADSTAGE(1, 1); CP_COMMIT();

    int mw = wid & 3, nw = wid >> 2;  // warp tile: rows mw*32, cols nw*64
    float acc[2][8][4];
#pragma unroll
    for (int f = 0; f < 2; f++)
#pragma unroll
        for (int g = 0; g < 8; g++)
#pragma unroll
            for (int q = 0; q < 4; q++) acc[f][g][q] = 0.f;

    int qrow = lane >> 2, qk = (lane & 3) * 2;

    for (int kc = 0; kc < NKCHUNK; kc++) {
        int st = kc & 1;
        CP_WAIT1();
        __syncthreads();
        uint32_t base = sb + st * GSTAGE;
#pragma unroll
        for (int kk = 0; kk < 32; kk += 16) {
            uint32_t ah[2][4], al[2][4];
#pragma unroll
            for (int f = 0; f < 2; f++) {
                uint32_t a0 = base + (mw * 32 + f * 16 + qrow) * 80 + (qk + kk) * 2;
                LDS32(ah[f][0], a0 + SA_H);
                LDS32(ah[f][1], a0 + SA_H + 8 * 80);
                LDS32(ah[f][2], a0 + SA_H + 16);
                LDS32(ah[f][3], a0 + SA_H + 8 * 80 + 16);
                LDS32(al[f][0], a0 + SA_L);
                LDS32(al[f][1], a0 + SA_L + 8 * 80);
                LDS32(al[f][2], a0 + SA_L + 16);
                LDS32(al[f][3], a0 + SA_L + 8 * 80 + 16);
            }
#pragma unroll
            for (int g = 0; g < 8; g++) {
                uint32_t bh[2], bl[2];
                uint32_t b0 = base + (nw * 64 + g * 8 + qrow) * 80 + (qk + kk) * 2;
                LDS32(bh[0], b0 + SB_H);
                LDS32(bh[1], b0 + SB_H + 16);
                LDS32(bl[0], b0 + SB_L);
                LDS32(bl[1], b0 + SB_L + 16);
#pragma unroll
                for (int f = 0; f < 2; f++) {
                    MMA_BF16(acc[f][g], ah[f], bh);
                    MMA_BF16(acc[f][g], ah[f], bl);
                    MMA_BF16(acc[f][g], al[f], bh);
                }
            }
        }
        __syncthreads();
        if (kc + 2 < NKCHUNK) LOADSTAGE(kc + 2, st);
        CP_COMMIT();
    }
#undef LOADSTAGE

    // epilogue: write fp32 partials
    float* part = g_f + OFF_PART + (size_t)ks * (N2 * 256);
#pragma unroll
    for (int f = 0; f < 2; f++) {
        int row = bm + mw * 32 + f * 16 + qrow;
#pragma unroll
        for (int g = 0; g < 8; g++) {
            int col = nw * 64 + g * 8 + (lane & 3) * 2;
            *(float2*)&part[(size_t)row * 256 + col] = make_float2(acc[f][g][0], acc[f][g][1]);
            *(float2*)&part[(size_t)(row + 8) * 256 + col] = make_float2(acc[f][g][2], acc[f][g][3]);
        }
    }
}

// ================= classifier =================

__global__ void k_fc(const float* __restrict__ fcw, const float* __restrict__ fcb) {
    int q = blockIdx.x / 6, c = blockIdx.x % 6;
    __shared__ float red[256];
    const float* y = g_f + OFF_Y2 + (size_t)q * 131072;
    const float* w = fcw + (size_t)c * 131072;
    float s = 0.f;
    for (int j = threadIdx.x; j < 131072; j += 256) s = fmaf(y[j], w[j], s);
    red[threadIdx.x] = s;
    __syncthreads();
    for (int o = 128; o > 0; o >>= 1) {
        if (threadIdx.x < o) red[threadIdx.x] += red[threadIdx.x + o];
        __syncthreads();
    }
    if (threadIdx.x == 0) g_f[OFF_LOG + q * 6 + c] = red[0] + fcb[c];
}

__global__ void k_lsm(float* out) {
    int t = threadIdx.x;
    if (t < 4) {
        float v[6];
        float m = -1e30f;
        for (int c = 0; c < 6; c++) { v[c] = g_f[OFF_LOG + t * 6 + c]; m = fmaxf(m, v[c]); }
        float se = 0.f;
        for (int c = 0; c < 6; c++) se += expf(v[c] - m);
        float l = logf(se);
        for (int c = 0; c < 6; c++) out[t * 6 + c] = v[c] - m - l;
    }
}

// ================= host =================

extern "C" void kernel_launch(void* const* d_in, const int* in_sizes, int n_in,
                              void* d_out, int out_size) {
    const float*     x    = (const float*)d_in[0];
    const void*      ei1  = d_in[1];
    const float*     w1e  = (const float*)d_in[2];
    const void*      ei2  = d_in[3];
    const float*     w2e  = (const float*)d_in[4];
    const float*     bmap = (const float*)d_in[5];
    const float*     W1   = (const float*)d_in[6];
    const float*     bias1= (const float*)d_in[7];
    const float*     W2   = (const float*)d_in[8];
    const float*     bias2= (const float*)d_in[9];
    const float*     fcw  = (const float*)d_in[10];
    const float*     fcb  = (const float*)d_in[11];
    float*           out  = (float*)d_out;
    (void)in_sizes; (void)n_in; (void)out_size;

    cudaFuncSetAttribute(k_gemm_mma, cudaFuncAttributeMaxDynamicSharedMemorySize, GSM_TOTAL);

    // --- preprocessing (8 launches) ---
    k_zero<<<(N1 + 255) / 256, 256>>>();
    k_detect<<<(E1C + 255) / 256, 256>>>((const long long*)ei1);
    k_decode2<<<(E1C + E2C + 255) / 256, 256>>>(ei1, ei2);
    k_count2<<<(E1C + E2C + 255) / 256, 256>>>();
    k_scan2<<<2, 1024>>>();
    k_fill2<<<(E1C + E2C + 255) / 256, 256>>>();
    k_sortdeg<<<(N1 + N2 + 127) / 128, 128>>>(w1e, w2e);
    k_norm2<<<(E1C + E2C + 255) / 256, 256>>>(w1e, w2e);
    k_convA<<<16384, 256>>>(bmap);   // independent of conv1

    // --- conv1: xpose+ein0, then 11 fused prop+ein steps ---
    int b1buf[3] = {OFF_T1, OFF_T1 + T1_STRIDE, OFF_T1 + 2 * T1_STRIDE};
    k_xpose_ein0<<<N1 / 8, 256>>>(x, W1, bias1);
    k_step1<<<N1 / 8, 256>>>(b1buf[0], b1buf[1], 0, 0, W1, 1);
    for (int k = 2; k < KCH; k++) {
        int in = b1buf[(k - 1) % 3], o = b1buf[k % 3], pv = b1buf[(k - 2) % 3];
        k_step1<<<N1 / 8, 256>>>(in, o, pv, 1, W1, k);
    }

    // --- split-bf16 mma GEMM (relu fused into convBT) ---
    k_convBT<<<512, 256>>>();
    dim3 gg(32, 4);
    k_gemm_mma<<<gg, 512, GSM_TOTAL>>>();

    // --- conv2: reduce+ein0, then 11 fused prop+ein steps ---
    int b2buf[3] = {OFF_T2, OFF_T2 + T2_STRIDE, OFF_T2 + 2 * T2_STRIDE};
    k_red_ein0<<<N2 / 8, 256>>>(W2, bias2);
    k_step2<<<N2 / 8, 256>>>(b2buf[0], b2buf[1], 0, 0, W2, 1);
    for (int k = 2; k < KCH; k++) {
        int in = b2buf[(k - 1) % 3], o = b2buf[k % 3], pv = b2buf[(k - 2) % 3];
        k_step2<<<N2 / 8, 256>>>(in, o, pv, 1, W2, k);
    }

    // --- fc + log_softmax ---
    k_fc<<<24, 256>>>(fcw, fcb);
    k_lsm<<<1, 32>>>(out);
}

// round 7
// speedup vs baseline: 2.2066x; 1.2000x over previous
#include <cuda_runtime.h>
#include <cuda_bf16.h>
#include <cstdint>
#include <stdint.h>
#include <math.h>

// ---------------- problem constants ----------------
#define N1   8192
#define N2   4096
#define TT   15
#define BS   4
#define E1C  131072
#define E2C  65536
#define KCH  12
#define G1C  64
#define G2C  32
#define NC   6

// ---------------- float scratch layout ----------------
#define T1_STRIDE (N1*64)
#define OFF_T1    0
#define OFF_Y1    (OFF_T1 + 3*T1_STRIDE)
#define T2_STRIDE (N2*256)
#define OFF_T2    (OFF_Y1 + N1*256)
#define OFF_Y2    (OFF_T2 + 3*T2_STRIDE)
#define OFF_NORM1 (OFF_Y2 + N2*128)
#define OFF_NORM2 (OFF_NORM1 + E1C)
#define OFF_DEG1  (OFF_NORM2 + E2C)
#define OFF_DEG2  (OFF_DEG1 + N1)
#define OFF_LOG   (OFF_DEG2 + N2)
#define OFF_FCP   (OFF_LOG + 64)
#define OFF_PART  (OFF_FCP + 256)
#define SCRATCH_F (OFF_PART + 4*N2*256)

__device__ float g_f[SCRATCH_F];

// bf16 split buffers for B^T only (A converted inline in the GEMM)
__device__ __nv_bfloat16 g_Bthi[(size_t)256 * N1]; // B^T: [256][8192]
__device__ __nv_bfloat16 g_Btlo[(size_t)256 * N1];

// ---------------- int scratch layout ----------------
#define IO_FLAG  0
#define IO_RP1   1
#define IO_CU1   (IO_RP1 + N1 + 1)
#define IO_EI1   (IO_CU1 + N1)
#define IO_SRC1  (IO_EI1 + E1C)
#define IO_DST1  (IO_SRC1 + E1C)
#define IO_RP2   (IO_DST1 + E1C)
#define IO_CU2   (IO_RP2 + N2 + 1)
#define IO_EI2   (IO_CU2 + N2)
#define IO_SRC2  (IO_EI2 + E2C)
#define IO_DST2  (IO_SRC2 + E2C)
#define SCRATCH_I (IO_DST2 + E2C)

__device__ int g_i[SCRATCH_I];

// ================= helpers =================

__device__ __forceinline__ uint32_t smem_u32(const void* p) {
    uint32_t a;
    asm("{ .reg .u64 t; cvta.to.shared.u64 t, %1; cvt.u32.u64 %0, t; }" : "=r"(a) : "l"(p));
    return a;
}

#define CP16(dst, src) \
    asm volatile("cp.async.cg.shared.global [%0], [%1], 16;" :: "r"(dst), "l"(src))
#define CP_COMMIT() asm volatile("cp.async.commit_group;" ::: "memory")
#define CP_WAIT1()  asm volatile("cp.async.wait_group 1;" ::: "memory")

#define LDS32(v, a) asm volatile("ld.shared.b32 %0, [%1];" : "=r"(v) : "r"(a))

#define MMA_BF16(c, a, b) \
    asm volatile("mma.sync.aligned.m16n8k16.row.col.f32.bf16.bf16.f32 " \
        "{%0,%1,%2,%3}, {%4,%5,%6,%7}, {%8,%9}, {%0,%1,%2,%3};" \
        : "+f"((c)[0]), "+f"((c)[1]), "+f"((c)[2]), "+f"((c)[3]) \
        : "r"((a)[0]), "r"((a)[1]), "r"((a)[2]), "r"((a)[3]), \
          "r"((b)[0]), "r"((b)[1]))

// split one fp32 into bf16 hi + bf16 lo(residual)
__device__ __forceinline__ void split_bf16(float v, unsigned short& h, unsigned short& l) {
    h = __bfloat16_as_ushort(__float2bfloat16(v));
    float r = v - __bfloat162float(__ushort_as_bfloat16(h));
    l = __bfloat16_as_ushort(__float2bfloat16(r));
}

// ================= preprocessing (merged) =================

__global__ void k_zero() {
    int i = blockIdx.x * blockDim.x + threadIdx.x;
    if (i == 0) g_i[IO_FLAG] = 0;
    if (i < N1) g_i[IO_CU1 + i] = 0;
    if (i < N2) g_i[IO_CU2 + i] = 0;
}

__global__ void k_detect(const long long* p) {
    int e = blockIdx.x * blockDim.x + threadIdx.x;
    if (e < E1C) {
        long long v = p[e];
        if (v < 0 || v >= (long long)N1) atomicOr(&g_i[IO_FLAG], 1);
    }
}

__global__ void k_decode2(const void* ei1, const void* ei2) {
    int e = blockIdx.x * blockDim.x + threadIdx.x;
    int is32 = g_i[IO_FLAG];
    const void* eiv; int E, srcOff, dstOff, le;
    if (e < E1C) { eiv = ei1; E = E1C; srcOff = IO_SRC1; dstOff = IO_DST1; le = e; }
    else if (e < E1C + E2C) { eiv = ei2; E = E2C; srcOff = IO_SRC2; dstOff = IO_DST2; le = e - E1C; }
    else return;
    int s, d;
    if (is32) {
        const int* p = (const int*)eiv;
        s = p[le]; d = p[E + le];
    } else {
        const long long* p = (const long long*)eiv;
        s = (int)p[le]; d = (int)p[E + le];
    }
    g_i[srcOff + le] = s;
    g_i[dstOff + le] = d;
}

__global__ void k_count2() {
    int e = blockIdx.x * blockDim.x + threadIdx.x;
    if (e < E1C) atomicAdd(&g_i[IO_CU1 + g_i[IO_DST1 + e]], 1);
    else if (e < E1C + E2C) atomicAdd(&g_i[IO_CU2 + g_i[IO_DST2 + e - E1C]], 1);
}

__global__ void k_scan2() {
    __shared__ int part[1024];
    int n, cntOff, rpOff;
    if (blockIdx.x == 0) { n = N1; cntOff = IO_CU1; rpOff = IO_RP1; }
    else                 { n = N2; cntOff = IO_CU2; rpOff = IO_RP2; }
    int t = threadIdx.x;
    int chunk = (n + 1023) >> 10;
    int base = t * chunk;
    int s = 0;
    for (int i = 0; i < chunk; i++) { int idx = base + i; if (idx < n) s += g_i[cntOff + idx]; }
    part[t] = s;
    __syncthreads();
    for (int off = 1; off < 1024; off <<= 1) {
        int v = (t >= off) ? part[t - off] : 0;
        __syncthreads();
        part[t] += v;
        __syncthreads();
    }
    int run = (t > 0) ? part[t - 1] : 0;
    for (int i = 0; i < chunk; i++) {
        int idx = base + i;
        if (idx < n) {
            int v = g_i[cntOff + idx];
            g_i[rpOff + idx] = run;
            g_i[cntOff + idx] = run;
            run += v;
        }
    }
    if (t == 1023) g_i[rpOff + n] = part[1023];
}

__global__ void k_fill2() {
    int e = blockIdx.x * blockDim.x + threadIdx.x;
    if (e < E1C) {
        int d = g_i[IO_DST1 + e];
        int p = atomicAdd(&g_i[IO_CU1 + d], 1);
        g_i[IO_EI1 + p] = e;
    } else if (e < E1C + E2C) {
        int le = e - E1C;
        int d = g_i[IO_DST2 + le];
        int p = atomicAdd(&g_i[IO_CU2 + d], 1);
        g_i[IO_EI2 + p] = le;
    }
}

__global__ void k_sortdeg(const float* w1, const float* w2) {
    int idx = blockIdx.x * blockDim.x + threadIdx.x;
    int rpOff, eidOff, degOff, node;
    const float* w;
    if (idx < N1) { node = idx; rpOff = IO_RP1; eidOff = IO_EI1; degOff = OFF_DEG1; w = w1; }
    else if (idx < N1 + N2) { node = idx - N1; rpOff = IO_RP2; eidOff = IO_EI2; degOff = OFF_DEG2; w = w2; }
    else return;
    int beg = g_i[rpOff + node], end = g_i[rpOff + node + 1];
    for (int i = beg + 1; i < end; i++) {
        int key = g_i[eidOff + i];
        int j = i - 1;
        while (j >= beg && g_i[eidOff + j] > key) {
            g_i[eidOff + j + 1] = g_i[eidOff + j];
            j--;
        }
        g_i[eidOff + j + 1] = key;
    }
    float s = 0.f;
    for (int i = beg; i < end; i++) s += w[g_i[eidOff + i]];
    g_f[degOff + node] = s;
}

__global__ void k_norm2(const float* w1, const float* w2) {
    int e = blockIdx.x * blockDim.x + threadIdx.x;
    int srcOff, dstOff, degOff, normOff, le;
    const float* w;
    if (e < E1C) { le = e; srcOff = IO_SRC1; dstOff = IO_DST1; degOff = OFF_DEG1; normOff = OFF_NORM1; w = w1; }
    else if (e < E1C + E2C) { le = e - E1C; srcOff = IO_SRC2; dstOff = IO_DST2; degOff = OFF_DEG2; normOff = OFF_NORM2; w = w2; }
    else return;
    float ds = g_f[degOff + g_i[srcOff + le]];
    float dd = g_f[degOff + g_i[dstOff + le]];
    float rs = (ds > 0.f) ? rsqrtf(ds) : 0.f;
    float rd = (dd > 0.f) ? rsqrtf(dd) : 0.f;
    g_f[normOff + le] = -w[le] * rs * rd;
}

// ================= conv1: fused kernels =================

__global__ void k_xpose_ein0(const float* __restrict__ x, const float* __restrict__ W1,
                             const float* __restrict__ bias1) {
    __shared__ float sW[TT * G1C];
    __shared__ float sT[8 * 64];
    int tid = threadIdx.x;
    int n0 = blockIdx.x * 8;
    for (int i = tid; i < TT * G1C; i += 256) sW[i] = W1[i];
#pragma unroll
    for (int it = 0; it < 2; it++) {
        int i = it * 256 + tid;
        int ns = i >> 6, j = i & 63;
        int d = j >> 2, b = j & 3;
        float v = (d < TT) ? x[(size_t)b * (N1 * TT) + (n0 + ns) * TT + d] : 0.f;
        sT[i] = v;
        g_f[OFF_T1 + (n0 + ns) * 64 + j] = v;
    }
    __syncthreads();
    int g = tid >> 2, b = tid & 3;
    float bv = bias1[g];
#pragma unroll
    for (int ns = 0; ns < 8; ns++) {
        float s = 0.f;
#pragma unroll
        for (int d = 0; d < TT; d++) s = fmaf(sT[ns * 64 + d * 4 + b], sW[d * G1C + g], s);
        g_f[OFF_Y1 + (n0 + ns) * 256 + tid] = s + bv;
    }
}

__global__ void k_step1(int inOff, int outOff, int prevOff, int dbl,
                        const float* __restrict__ W1, int k) {
    __shared__ float sW[TT * G1C];
    __shared__ float sT[8 * 64];
    int tid = threadIdx.x;
    for (int i = tid; i < TT * G1C; i += 256) sW[i] = W1[k * TT * G1C + i];
    int warp = tid >> 5, lane = tid & 31;
    int node = blockIdx.x * 8 + warp;
    int half = lane >> 4, c4 = lane & 15;
    int beg = g_i[IO_RP1 + node], end = g_i[IO_RP1 + node + 1];
    const float4* in = (const float4*)(g_f + inOff);
    float4 acc = make_float4(0.f, 0.f, 0.f, 0.f);
    for (int i = beg + half; i < end; i += 2) {
        int e = g_i[IO_EI1 + i];
        float nm = g_f[OFF_NORM1 + e];
        int s = g_i[IO_SRC1 + e];
        float4 v = in[s * 16 + c4];
        acc.x = fmaf(nm, v.x, acc.x);
        acc.y = fmaf(nm, v.y, acc.y);
        acc.z = fmaf(nm, v.z, acc.z);
        acc.w = fmaf(nm, v.w, acc.w);
    }
    acc.x += __shfl_down_sync(0xffffffffu, acc.x, 16);
    acc.y += __shfl_down_sync(0xffffffffu, acc.y, 16);
    acc.z += __shfl_down_sync(0xffffffffu, acc.z, 16);
    acc.w += __shfl_down_sync(0xffffffffu, acc.w, 16);
    if (half == 0) {
        float4 r = acc;
        if (dbl) {
            float4 p = ((const float4*)(g_f + prevOff))[node * 16 + c4];
            r.x = 2.f * r.x - p.x;
            r.y = 2.f * r.y - p.y;
            r.z = 2.f * r.z - p.z;
            r.w = 2.f * r.w - p.w;
        }
        ((float4*)(g_f + outOff))[node * 16 + c4] = r;
        *(float4*)&sT[warp * 64 + c4 * 4] = r;
    }
    __syncthreads();
    int g = tid >> 2, b = tid & 3;
    int n0 = blockIdx.x * 8;
#pragma unroll
    for (int ns = 0; ns < 8; ns++) {
        float s = 0.f;
#pragma unroll
        for (int d = 0; d < TT; d++) s = fmaf(sT[ns * 64 + d * 4 + b], sW[d * G1C + g], s);
        g_f[OFF_Y1 + (n0 + ns) * 256 + tid] += s;
    }
}

// ================= conv2: fused kernels =================

__global__ void k_red_ein0(const float* __restrict__ W2, const float* __restrict__ bias2) {
    __shared__ float sW[G1C * G2C];
    __shared__ float sT[8 * 256];
    int tid = threadIdx.x;
    int n0 = blockIdx.x * 8;
    for (int i = tid; i < G1C * G2C; i += 256) sW[i] = W2[i];
#pragma unroll
    for (int ns = 0; ns < 8; ns++) {
        size_t gi = (size_t)(n0 + ns) * 256 + tid;
        float v = g_f[OFF_PART + gi] + g_f[OFF_PART + (N2 * 256) + gi]
                + g_f[OFF_PART + 2 * (N2 * 256) + gi] + g_f[OFF_PART + 3 * (N2 * 256) + gi];
        g_f[OFF_T2 + gi] = v;
        sT[ns * 256 + tid] = v;
    }
    __syncthreads();
    int local = tid & 127, sub = tid >> 7;
    int g = local >> 2, b = local & 3;
    float bv = bias2[g];
#pragma unroll
    for (int pass = 0; pass < 4; pass++) {
        int ns = pass * 2 + sub;
        float s = 0.f;
#pragma unroll
        for (int d = 0; d < G1C; d++) s = fmaf(sT[ns * 256 + d * 4 + b], sW[d * G2C + g], s);
        g_f[OFF_Y2 + (n0 + ns) * 128 + local] = s + bv;
    }
}

__global__ void k_step2(int inOff, int outOff, int prevOff, int dbl,
                        const float* __restrict__ W2, int k) {
    __shared__ float sW[G1C * G2C];
    __shared__ float sT[8 * 256];
    int tid = threadIdx.x;
    for (int i = tid; i < G1C * G2C; i += 256) sW[i] = W2[k * G1C * G2C + i];
    int warp = tid >> 5, lane = tid & 31;
    int node = blockIdx.x * 8 + warp;
    int beg = g_i[IO_RP2 + node], end = g_i[IO_RP2 + node + 1];
    const float4* in = (const float4*)(g_f + inOff);
    float4 a0 = make_float4(0.f, 0.f, 0.f, 0.f);
    float4 a1 = a0;
    for (int i = beg; i < end; i++) {
        int e = g_i[IO_EI2 + i];
        float nm = g_f[OFF_NORM2 + e];
        int s = g_i[IO_SRC2 + e];
        const float4* row = in + s * 64;
        float4 v0 = row[lane], v1 = row[lane + 32];
        a0.x = fmaf(nm, v0.x, a0.x); a0.y = fmaf(nm, v0.y, a0.y);
        a0.z = fmaf(nm, v0.z, a0.z); a0.w = fmaf(nm, v0.w, a0.w);
        a1.x = fmaf(nm, v1.x, a1.x); a1.y = fmaf(nm, v1.y, a1.y);
        a1.z = fmaf(nm, v1.z, a1.z); a1.w = fmaf(nm, v1.w, a1.w);
    }
    if (dbl) {
        const float4* pv = (const float4*)(g_f + prevOff) + node * 64;
        float4 p0 = pv[lane], p1 = pv[lane + 32];
        a0.x = 2.f * a0.x - p0.x; a0.y = 2.f * a0.y - p0.y;
        a0.z = 2.f * a0.z - p0.z; a0.w = 2.f * a0.w - p0.w;
        a1.x = 2.f * a1.x - p1.x; a1.y = 2.f * a1.y - p1.y;
        a1.z = 2.f * a1.z - p1.z; a1.w = 2.f * a1.w - p1.w;
    }
    float4* o = (float4*)(g_f + outOff) + node * 64;
    o[lane] = a0;
    o[lane + 32] = a1;
    *(float4*)&sT[warp * 256 + lane * 4] = a0;
    *(float4*)&sT[warp * 256 + 128 + lane * 4] = a1;
    __syncthreads();
    int local = tid & 127, sub = tid >> 7;
    int g = local >> 2, b = local & 3;
    int n0 = blockIdx.x * 8;
#pragma unroll
    for (int pass = 0; pass < 4; pass++) {
        int ns = pass * 2 + sub;
        float s = 0.f;
#pragma unroll
        for (int d = 0; d < G1C; d++) s = fmaf(sT[ns * 256 + d * 4 + b], sW[d * G2C + g], s);
        g_f[OFF_Y2 + (n0 + ns) * 128 + local] += s;
    }
}

// ================= B^T split conversion (relu fused) =================

__global__ void k_convBT() {
    __shared__ float s[64][65];
    int kt = blockIdx.x >> 2, nt = blockIdx.x & 3;
    int k0 = kt * 64, n0 = nt * 64;
    int t = threadIdx.x;
    {
        int r = t >> 4, c4 = t & 15;
#pragma unroll
        for (int i = 0; i < 4; i++) {
            int row = r + i * 16;
            float4 v = *(const float4*)&g_f[OFF_Y1 + (size_t)(k0 + row) * 256 + n0 + c4 * 4];
            s[row][c4 * 4 + 0] = fmaxf(v.x, 0.f);
            s[row][c4 * 4 + 1] = fmaxf(v.y, 0.f);
            s[row][c4 * 4 + 2] = fmaxf(v.z, 0.f);
            s[row][c4 * 4 + 3] = fmaxf(v.w, 0.f);
        }
    }
    __syncthreads();
    int n = t >> 2, kc = t & 3;
    unsigned short h[16], l[16];
#pragma unroll
    for (int e = 0; e < 16; e++) {
        split_bf16(s[kc * 16 + e][n], h[e], l[e]);
    }
    size_t ob = (size_t)(n0 + n) * N1 + k0 + kc * 16;
    uint4* dh = (uint4*)(g_Bthi + ob);
    uint4* dl = (uint4*)(g_Btlo + ob);
#pragma unroll
    for (int half = 0; half < 2; half++) {
        int e0 = half * 8;
        dh[half] = make_uint4((uint32_t)h[e0] | ((uint32_t)h[e0+1] << 16),
                              (uint32_t)h[e0+2] | ((uint32_t)h[e0+3] << 16),
                              (uint32_t)h[e0+4] | ((uint32_t)h[e0+5] << 16),
                              (uint32_t)h[e0+6] | ((uint32_t)h[e0+7] << 16));
        dl[half] = make_uint4((uint32_t)l[e0] | ((uint32_t)l[e0+1] << 16),
                              (uint32_t)l[e0+2] | ((uint32_t)l[e0+3] << 16),
                              (uint32_t)l[e0+4] | ((uint32_t)l[e0+5] << 16),
                              (uint32_t)l[e0+6] | ((uint32_t)l[e0+7] << 16));
    }
}

// ================= mma.sync split-bf16 GEMM (A converted inline) =================
// C(4096x256) = A(4096x8192) * B(8192x256), 3-product split-bf16, fp32 acc.
// Grid (mt=32, ks=4). CTA tile 128M x 256N, K slice 2048, 16 warps (warp 32x64).
// A: fp32 LDG -> reg split -> STS bf16 hi/lo. B: cp.async from pre-split buffers.

#define SA_H 0
#define SA_L 10240
#define SB_H 20480
#define SB_L 40960
#define GSTAGE 61440
#define GSM_TOTAL (2 * GSTAGE)
#define NKCHUNK 64   // 2048 / 32

__global__ void __launch_bounds__(512, 1) k_gemm_mma(const float* __restrict__ Agl) {
    extern __shared__ char smem[];
    uint32_t sb = smem_u32(smem);
    int tid = threadIdx.x, lane = tid & 31, wid = tid >> 5;
    int mt = blockIdx.x, ks = blockIdx.y;
    int bm = mt * 128;
    int kbase = ks * 2048;

    const __nv_bfloat16* Bh = g_Bthi;
    const __nv_bfloat16* Bl = g_Btlo;

    int arow = tid >> 2, ach = tid & 3;   // A: 128 rows x 4 chunks of 8 elems
    int brow = tid >> 1, bch = tid & 1;   // B: 256 rows x 2 chunk-pairs
    const float* Arow = Agl + (size_t)(bm + arow) * N1 + kbase + ach * 8;

#define LOADB(kc, st) do { \
        int kb_ = kbase + (kc) * 32 + bch * 16; \
        uint32_t db_ = sb + (st) * GSTAGE + brow * 80 + bch * 32; \
        CP16(db_ + SB_H,      Bh + (size_t)brow * N1 + kb_); \
        CP16(db_ + SB_H + 16, Bh + (size_t)brow * N1 + kb_ + 8); \
        CP16(db_ + SB_L,      Bl + (size_t)brow * N1 + kb_); \
        CP16(db_ + SB_L + 16, Bl + (size_t)brow * N1 + kb_ + 8); \
    } while (0)

#define STS_A(v0, v1, st) do { \
        unsigned short h_[8], l_[8]; \
        split_bf16((v0).x, h_[0], l_[0]); split_bf16((v0).y, h_[1], l_[1]); \
        split_bf16((v0).z, h_[2], l_[2]); split_bf16((v0).w, h_[3], l_[3]); \
        split_bf16((v1).x, h_[4], l_[4]); split_bf16((v1).y, h_[5], l_[5]); \
        split_bf16((v1).z, h_[6], l_[6]); split_bf16((v1).w, h_[7], l_[7]); \
        uint32_t da_ = sb + (st) * GSTAGE + arow * 80 + ach * 16; \
        *(uint4*)(smem + (da_ - sb) + SA_H) = make_uint4( \
            (uint32_t)h_[0] | ((uint32_t)h_[1] << 16), (uint32_t)h_[2] | ((uint32_t)h_[3] << 16), \
            (uint32_t)h_[4] | ((uint32_t)h_[5] << 16), (uint32_t)h_[6] | ((uint32_t)h_[7] << 16)); \
        *(uint4*)(smem + (da_ - sb) + SA_L) = make_uint4( \
            (uint32_t)l_[0] | ((uint32_t)l_[1] << 16), (uint32_t)l_[2] | ((uint32_t)l_[3] << 16), \
            (uint32_t)l_[4] | ((uint32_t)l_[5] << 16), (uint32_t)l_[6] | ((uint32_t)l_[7] << 16)); \
    } while (0)

    // prologue: A(0)->stage0, A(1)->stage1 (STS), B(0),B(1) via cp.async
    {
        float4 a0 = *(const float4*)(Arow + 0 * 32);
        float4 a1 = *(const float4*)(Arow + 0 * 32 + 4);
        STS_A(a0, a1, 0);
        float4 b0 = *(const float4*)(Arow + 1 * 32);
        float4 b1 = *(const float4*)(Arow + 1 * 32 + 4);
        STS_A(b0, b1, 1);
    }
    LOADB(0, 0); CP_COMMIT();
    LOADB(1, 1); CP_COMMIT();

    int mw = wid & 3, nw = wid >> 2;  // warp tile: rows mw*32, cols nw*64
    float acc[2][8][4];
#pragma unroll
    for (int f = 0; f < 2; f++)
#pragma unroll
        for (int g = 0; g < 8; g++)
#pragma unroll
            for (int q = 0; q < 4; q++) acc[f][g][q] = 0.f;

    int qrow = lane >> 2, qk = (lane & 3) * 2;

    for (int kc = 0; kc < NKCHUNK; kc++) {
        int st = kc & 1;
        CP_WAIT1();
        __syncthreads();
        // prefetch A(kc+2) fp32 (hidden under MMA body)
        float4 pa0, pa1;
        bool pre = (kc + 2 < NKCHUNK);
        if (pre) {
            pa0 = *(const float4*)(Arow + (kc + 2) * 32);
            pa1 = *(const float4*)(Arow + (kc + 2) * 32 + 4);
        }
        uint32_t base = sb + st * GSTAGE;
#pragma unroll
        for (int kk = 0; kk < 32; kk += 16) {
            uint32_t ah[2][4], al[2][4];
#pragma unroll
            for (int f = 0; f < 2; f++) {
                uint32_t a0 = base + (mw * 32 + f * 16 + qrow) * 80 + (qk + kk) * 2;
                LDS32(ah[f][0], a0 + SA_H);
                LDS32(ah[f][1], a0 + SA_H + 8 * 80);
                LDS32(ah[f][2], a0 + SA_H + 16);
                LDS32(ah[f][3], a0 + SA_H + 8 * 80 + 16);
                LDS32(al[f][0], a0 + SA_L);
                LDS32(al[f][1], a0 + SA_L + 8 * 80);
                LDS32(al[f][2], a0 + SA_L + 16);
                LDS32(al[f][3], a0 + SA_L + 8 * 80 + 16);
            }
#pragma unroll
            for (int g = 0; g < 8; g++) {
                uint32_t bh[2], bl[2];
                uint32_t b0 = base + (nw * 64 + g * 8 + qrow) * 80 + (qk + kk) * 2;
                LDS32(bh[0], b0 + SB_H);
                LDS32(bh[1], b0 + SB_H + 16);
                LDS32(bl[0], b0 + SB_L);
                LDS32(bl[1], b0 + SB_L + 16);
#pragma unroll
                for (int f = 0; f < 2; f++) {
                    MMA_BF16(acc[f][g], ah[f], bh);
                    MMA_BF16(acc[f][g], ah[f], bl);
                    MMA_BF16(acc[f][g], al[f], bh);
                }
            }
        }
        __syncthreads();
        if (pre) {
            STS_A(pa0, pa1, st);
            LOADB(kc + 2, st);
        }
        CP_COMMIT();
    }
#undef LOADB
#undef STS_A

    // epilogue: write fp32 partials
    float* part = g_f + OFF_PART + (size_t)ks * (N2 * 256);
#pragma unroll
    for (int f = 0; f < 2; f++) {
        int row = bm + mw * 32 + f * 16 + qrow;
#pragma unroll
        for (int g = 0; g < 8; g++) {
            int col = nw * 64 + g * 8 + (lane & 3) * 2;
            *(float2*)&part[(size_t)row * 256 + col] = make_float2(acc[f][g][0], acc[f][g][1]);
            *(float2*)&part[(size_t)(row + 8) * 256 + col] = make_float2(acc[f][g][2], acc[f][g][3]);
        }
    }
}

// ================= classifier =================

// split-K fc: grid 192 = q(4) * c(6) * ks(8); 256 threads; float4 loads
__global__ void k_fc(const float* __restrict__ fcw) {
    int blk = blockIdx.x;
    int q = blk / 48, rem = blk % 48, c = rem / 8, ks = rem % 8;
    __shared__ float red[256];
    const float4* y = (const float4*)(g_f + OFF_Y2 + (size_t)q * 131072 + ks * 16384);
    const float4* w = (const float4*)(fcw + (size_t)c * 131072 + ks * 16384);
    float s = 0.f;
#pragma unroll
    for (int it = 0; it < 16; it++) {
        int j = it * 256 + threadIdx.x;
        float4 a = y[j], b = w[j];
        s = fmaf(a.x, b.x, s); s = fmaf(a.y, b.y, s);
        s = fmaf(a.z, b.z, s); s = fmaf(a.w, b.w, s);
    }
    red[threadIdx.x] = s;
    __syncthreads();
    for (int o = 128; o > 0; o >>= 1) {
        if (threadIdx.x < o) red[threadIdx.x] += red[threadIdx.x + o];
        __syncthreads();
    }
    if (threadIdx.x == 0) g_f[OFF_FCP + blk] = red[0];
}

__global__ void k_lsm(const float* __restrict__ fcb, float* out) {
    __shared__ float logit[24];
    int t = threadIdx.x;
    if (t < 24) {
        int q = t / 6, c = t % 6;
        float s = fcb[c];
#pragma unroll
        for (int i = 0; i < 8; i++) s += g_f[OFF_FCP + q * 48 + c * 8 + i];
        logit[t] = s;
    }
    __syncwarp();
    if (t < 4) {
        float m = -1e30f;
        for (int c = 0; c < 6; c++) m = fmaxf(m, logit[t * 6 + c]);
        float se = 0.f;
        for (int c = 0; c < 6; c++) se += expf(logit[t * 6 + c] - m);
        float l = logf(se);
        for (int c = 0; c < 6; c++) out[t * 6 + c] = logit[t * 6 + c] - m - l;
    }
}

// ================= host =================

extern "C" void kernel_launch(void* const* d_in, const int* in_sizes, int n_in,
                              void* d_out, int out_size) {
    const float*     x    = (const float*)d_in[0];
    const void*      ei1  = d_in[1];
    const float*     w1e  = (const float*)d_in[2];
    const void*      ei2  = d_in[3];
    const float*     w2e  = (const float*)d_in[4];
    const float*     bmap = (const float*)d_in[5];
    const float*     W1   = (const float*)d_in[6];
    const float*     bias1= (const float*)d_in[7];
    const float*     W2   = (const float*)d_in[8];
    const float*     bias2= (const float*)d_in[9];
    const float*     fcw  = (const float*)d_in[10];
    const float*     fcb  = (const float*)d_in[11];
    float*           out  = (float*)d_out;
    (void)in_sizes; (void)n_in; (void)out_size;

    cudaFuncSetAttribute(k_gemm_mma, cudaFuncAttributeMaxDynamicSharedMemorySize, GSM_TOTAL);

    // --- preprocessing (8 launches) ---
    k_zero<<<(N1 + 255) / 256, 256>>>();
    k_detect<<<(E1C + 255) / 256, 256>>>((const long long*)ei1);
    k_decode2<<<(E1C + E2C + 255) / 256, 256>>>(ei1, ei2);
    k_count2<<<(E1C + E2C + 255) / 256, 256>>>();
    k_scan2<<<2, 1024>>>();
    k_fill2<<<(E1C + E2C + 255) / 256, 256>>>();
    k_sortdeg<<<(N1 + N2 + 127) / 128, 128>>>(w1e, w2e);
    k_norm2<<<(E1C + E2C + 255) / 256, 256>>>(w1e, w2e);

    // --- conv1: xpose+ein0, then 11 fused prop+ein steps ---
    int b1buf[3] = {OFF_T1, OFF_T1 + T1_STRIDE, OFF_T1 + 2 * T1_STRIDE};
    k_xpose_ein0<<<N1 / 8, 256>>>(x, W1, bias1);
    k_step1<<<N1 / 8, 256>>>(b1buf[0], b1buf[1], 0, 0, W1, 1);
    for (int k = 2; k < KCH; k++) {
        int in = b1buf[(k - 1) % 3], o = b1buf[k % 3], pv = b1buf[(k - 2) % 3];
        k_step1<<<N1 / 8, 256>>>(in, o, pv, 1, W1, k);
    }

    // --- split-bf16 mma GEMM (A converted inline; relu fused into convBT) ---
    k_convBT<<<512, 256>>>();
    dim3 gg(32, 4);
    k_gemm_mma<<<gg, 512, GSM_TOTAL>>>(bmap);

    // --- conv2: reduce+ein0, then 11 fused prop+ein steps ---
    int b2buf[3] = {OFF_T2, OFF_T2 + T2_STRIDE, OFF_T2 + 2 * T2_STRIDE};
    k_red_ein0<<<N2 / 8, 256>>>(W2, bias2);
    k_step2<<<N2 / 8, 256>>>(b2buf[0], b2buf[1], 0, 0, W2, 1);
    for (int k = 2; k < KCH; k++) {
        int in = b2buf[(k - 1) % 3], o = b2buf[k % 3], pv = b2buf[(k - 2) % 3];
        k_step2<<<N2 / 8, 256>>>(in, o, pv, 1, W2, k);
    }

    // --- fc + log_softmax ---
    k_fc<<<192, 256>>>(fcw);
    k_lsm<<<1, 32>>>(fcb, out);
}